// round 3
// baseline (speedup 1.0000x reference)
#include <cuda_runtime.h>

// ---------------------------------------------------------------------------
// GraphConvLayer: fused fp32 implementation, v2 (512-thread blocks)
//   K0a: convert edge_index (int32 OR int64, auto-detected) -> g_src/g_dst
//   K0b: zero g_agg scratch
//   K1 : edge MLP, 128 edges/block, 512 thr, 8x4 tile      ~33 GMAC
//   K2 : node MLP,  64 nodes/block, 512 thr, 4x4 tile       ~2.5 GMAC
// ---------------------------------------------------------------------------

#define MAX_N 50000
#define MAX_E 800000
#define ND 128
#define BE 128      // edges per block

// device-global scratch (allocations are forbidden)
__device__ float g_agg[(size_t)MAX_N * ND];
__device__ int   g_src[MAX_E];
__device__ int   g_dst[MAX_E];

// ---------------------------------------------------------------------------
// Index conversion: detect int64 vs int32 materialization of edge_index.
// ---------------------------------------------------------------------------
__global__ void convert_idx_kernel(const void* __restrict__ ei, int E)
{
    const int* p32 = (const int*)ei;
    int s = 0;
    #pragma unroll
    for (int i = 0; i < 16; ++i) s |= p32[2 * i + 1];
    const bool is64 = (s == 0);

    const int stride = gridDim.x * blockDim.x;
    if (is64) {
        const long long* p = (const long long*)ei;
        for (int i = blockIdx.x * blockDim.x + threadIdx.x; i < E; i += stride) {
            g_src[i] = (int)p[i];
            g_dst[i] = (int)p[(size_t)E + i];
        }
    } else {
        for (int i = blockIdx.x * blockDim.x + threadIdx.x; i < E; i += stride) {
            g_src[i] = p32[i];
            g_dst[i] = p32[(size_t)E + i];
        }
    }
}

__global__ void zero_agg_kernel(int n4) {
    float4 z = make_float4(0.f, 0.f, 0.f, 0.f);
    float4* p = (float4*)g_agg;
    for (int i = blockIdx.x * blockDim.x + threadIdx.x; i < n4;
         i += gridDim.x * blockDim.x)
        p[i] = z;
}

__device__ __forceinline__ float lrelu(float v) {
    return v >= 0.f ? v : 0.2f * v;
}

// ---------------------------------------------------------------------------
// Edge kernel: BE=128 edges per block, 512 threads (16 warps, 4/SMSP).
// smem phase A: W1 (192x128 = 24576 f) | X (128x192 = 24576 f)  -> 196608 B
// smem phase B: H (128x128 = 16384 f) + W2 (128x128 = 16384 f) overlay
// thread (tc = tid&31, tr = tid>>5): 8 rows x 4 cols register tile
// ---------------------------------------------------------------------------
__global__ __launch_bounds__(512, 1)
void edge_mlp_kernel(const float* __restrict__ node_feats,
                     const float* __restrict__ edge_feats,
                     const float* __restrict__ w1, const float* __restrict__ b1,
                     const float* __restrict__ w2, const float* __restrict__ b2,
                     int E)
{
    extern __shared__ float sm[];
    float* sW = sm;               // phase A: W1 [192][128]
    float* sX = sm + 24576;       // X tile, row stride 192

    __shared__ int s_src[BE];
    __shared__ int s_dst[BE];

    const int tid = threadIdx.x;
    const int e0  = blockIdx.x * BE;

    if (tid < BE) {
        int e = e0 + tid;
        if (e < E) { s_src[tid] = g_src[e]; s_dst[tid] = g_dst[e]; }
        else       { s_src[tid] = -1;       s_dst[tid] = -1; }
    }
    // stage W1 (6144 float4)
    {
        const float4* g = (const float4*)w1;
        float4* s = (float4*)sW;
        for (int i = tid; i < 6144; i += 512) s[i] = g[i];
    }
    __syncthreads();   // s_dst visible before X staging

    // stage X: per edge 48 float4 (32 from node_feats[dst], 16 from edge_feats)
    for (int i = tid; i < BE * 48; i += 512) {
        int e = i / 48, q = i - e * 48;
        float4 v = make_float4(0.f, 0.f, 0.f, 0.f);
        int d = s_dst[e];
        if (d >= 0) {
            if (q < 32) v = ((const float4*)(node_feats + (size_t)d * ND))[q];
            else        v = ((const float4*)(edge_feats + (size_t)(e0 + e) * 64))[q - 32];
        }
        ((float4*)(sX + e * 192))[q] = v;
    }
    __syncthreads();

    const int tc = tid & 31;
    const int tr = tid >> 5;
    const int r0 = tr * 8;        // 16 warps x 8 rows = 128 rows

    // ---- GEMM1: h = lrelu(X @ W1 + b1), K = 192 ----
    float acc[8][4];
    {
        float4 bv = ((const float4*)b1)[tc];
        #pragma unroll
        for (int i = 0; i < 8; ++i) {
            acc[i][0] = bv.x; acc[i][1] = bv.y; acc[i][2] = bv.z; acc[i][3] = bv.w;
        }
    }
    {
        const float4* W4 = (const float4*)sW;   // [192][32]
        for (int k = 0; k < 192; k += 4) {
            float4 wa = W4[(k + 0) * 32 + tc];
            float4 wb = W4[(k + 1) * 32 + tc];
            float4 wc = W4[(k + 2) * 32 + tc];
            float4 wd = W4[(k + 3) * 32 + tc];
            #pragma unroll
            for (int i = 0; i < 8; ++i) {
                float4 x = ((const float4*)(sX + (r0 + i) * 192))[k >> 2];
                acc[i][0] += x.x * wa.x + x.y * wb.x + x.z * wc.x + x.w * wd.x;
                acc[i][1] += x.x * wa.y + x.y * wb.y + x.z * wc.y + x.w * wd.y;
                acc[i][2] += x.x * wa.z + x.y * wb.z + x.z * wc.z + x.w * wd.z;
                acc[i][3] += x.x * wa.w + x.y * wb.w + x.z * wc.w + x.w * wd.w;
            }
        }
    }
    #pragma unroll
    for (int i = 0; i < 8; ++i) {
        #pragma unroll
        for (int j = 0; j < 4; ++j) acc[i][j] = lrelu(acc[i][j]);
    }

    __syncthreads();   // done reading sW/sX before overlay

    // ---- phase B: H + W2 overlay ----
    float* sH  = sm;          // 128x128
    float* sW2 = sm + 16384;  // 128x128
    #pragma unroll
    for (int i = 0; i < 8; ++i)
        ((float4*)(sH + (r0 + i) * ND))[tc] =
            make_float4(acc[i][0], acc[i][1], acc[i][2], acc[i][3]);
    {
        const float4* g = (const float4*)w2;
        float4* s = (float4*)sW2;
        for (int i = tid; i < 4096; i += 512) s[i] = g[i];
    }
    __syncthreads();

    // ---- GEMM2: msg = H @ W2 + b2, K = 128 ----
    float acc2[8][4];
    {
        float4 bv = ((const float4*)b2)[tc];
        #pragma unroll
        for (int i = 0; i < 8; ++i) {
            acc2[i][0] = bv.x; acc2[i][1] = bv.y; acc2[i][2] = bv.z; acc2[i][3] = bv.w;
        }
    }
    {
        const float4* W4 = (const float4*)sW2;  // [128][32]
        for (int k = 0; k < 128; k += 4) {
            float4 wa = W4[(k + 0) * 32 + tc];
            float4 wb = W4[(k + 1) * 32 + tc];
            float4 wc = W4[(k + 2) * 32 + tc];
            float4 wd = W4[(k + 3) * 32 + tc];
            #pragma unroll
            for (int i = 0; i < 8; ++i) {
                float4 x = ((const float4*)(sH + (r0 + i) * ND))[k >> 2];
                acc2[i][0] += x.x * wa.x + x.y * wb.x + x.z * wc.x + x.w * wd.x;
                acc2[i][1] += x.x * wa.y + x.y * wb.y + x.z * wc.y + x.w * wd.y;
                acc2[i][2] += x.x * wa.z + x.y * wb.z + x.z * wc.z + x.w * wd.z;
                acc2[i][3] += x.x * wa.w + x.y * wb.w + x.z * wc.w + x.w * wd.w;
            }
        }
    }

    // ---- scatter-add messages to src nodes ----
    const int c0 = tc * 4;
    #pragma unroll
    for (int i = 0; i < 8; ++i) {
        int s = s_src[r0 + i];
        if (s >= 0) {
            float* p = g_agg + (size_t)s * ND + c0;
            atomicAdd(p + 0, acc2[i][0]);
            atomicAdd(p + 1, acc2[i][1]);
            atomicAdd(p + 2, acc2[i][2]);
            atomicAdd(p + 3, acc2[i][3]);
        }
    }
}

// ---------------------------------------------------------------------------
// Node kernel: 64 nodes per block, 512 threads (16 warps), 4x4 tile.
// smem phase A: W1 (256x128 = 32768 f) | X (64x256 = 16384 f)   -> 196608 B
// smem phase B: H (8192 f) + W2 (16384 f) overlay
// ---------------------------------------------------------------------------
__global__ __launch_bounds__(512, 1)
void node_mlp_kernel(const float* __restrict__ node_feats,
                     const float* __restrict__ w1, const float* __restrict__ b1,
                     const float* __restrict__ w2, const float* __restrict__ b2,
                     float* __restrict__ out, int N)
{
    extern __shared__ float sm[];
    float* sW = sm;               // W1 256x128
    float* sX = sm + 32768;       // X 64x256

    const int tid = threadIdx.x;
    const int n0  = blockIdx.x * 64;

    // stage W1 (8192 float4)
    {
        const float4* g = (const float4*)w1;
        float4* s = (float4*)sW;
        for (int i = tid; i < 8192; i += 512) s[i] = g[i];
    }
    // stage X: per node 64 float4 (32 node_feats + 32 g_agg)
    for (int i = tid; i < 64 * 64; i += 512) {
        int r = i >> 6, q = i & 63;
        int n = n0 + r;
        float4 v = make_float4(0.f, 0.f, 0.f, 0.f);
        if (n < N) {
            if (q < 32) v = ((const float4*)(node_feats + (size_t)n * ND))[q];
            else        v = ((const float4*)(g_agg + (size_t)n * ND))[q - 32];
        }
        ((float4*)(sX + r * 256))[q] = v;
    }
    __syncthreads();

    const int tc = tid & 31;
    const int tr = tid >> 5;
    const int r0 = tr * 4;        // 16 warps x 4 rows = 64 rows

    // ---- GEMM1: h2 = lrelu(X @ W1 + b1), K = 256 ----
    float acc[4][4];
    {
        float4 bv = ((const float4*)b1)[tc];
        #pragma unroll
        for (int i = 0; i < 4; ++i) {
            acc[i][0] = bv.x; acc[i][1] = bv.y; acc[i][2] = bv.z; acc[i][3] = bv.w;
        }
    }
    {
        const float4* W4 = (const float4*)sW;   // [256][32]
        for (int k = 0; k < 256; k += 4) {
            float4 wa = W4[(k + 0) * 32 + tc];
            float4 wb = W4[(k + 1) * 32 + tc];
            float4 wc = W4[(k + 2) * 32 + tc];
            float4 wd = W4[(k + 3) * 32 + tc];
            #pragma unroll
            for (int i = 0; i < 4; ++i) {
                float4 x = ((const float4*)(sX + (r0 + i) * 256))[k >> 2];
                acc[i][0] += x.x * wa.x + x.y * wb.x + x.z * wc.x + x.w * wd.x;
                acc[i][1] += x.x * wa.y + x.y * wb.y + x.z * wc.y + x.w * wd.y;
                acc[i][2] += x.x * wa.z + x.y * wb.z + x.z * wc.z + x.w * wd.z;
                acc[i][3] += x.x * wa.w + x.y * wb.w + x.z * wc.w + x.w * wd.w;
            }
        }
    }
    #pragma unroll
    for (int i = 0; i < 4; ++i) {
        #pragma unroll
        for (int j = 0; j < 4; ++j) acc[i][j] = lrelu(acc[i][j]);
    }

    __syncthreads();

    float* sH  = sm;          // 64x128
    float* sW2 = sm + 8192;   // 128x128
    #pragma unroll
    for (int i = 0; i < 4; ++i)
        ((float4*)(sH + (r0 + i) * ND))[tc] =
            make_float4(acc[i][0], acc[i][1], acc[i][2], acc[i][3]);
    {
        const float4* g = (const float4*)w2;
        float4* s = (float4*)sW2;
        for (int i = tid; i < 4096; i += 512) s[i] = g[i];
    }
    __syncthreads();

    // ---- GEMM2: out = H @ W2 + b2, K = 128 ----
    float acc2[4][4];
    {
        float4 bv = ((const float4*)b2)[tc];
        #pragma unroll
        for (int i = 0; i < 4; ++i) {
            acc2[i][0] = bv.x; acc2[i][1] = bv.y; acc2[i][2] = bv.z; acc2[i][3] = bv.w;
        }
    }
    {
        const float4* W4 = (const float4*)sW2;  // [128][32]
        for (int k = 0; k < 128; k += 4) {
            float4 wa = W4[(k + 0) * 32 + tc];
            float4 wb = W4[(k + 1) * 32 + tc];
            float4 wc = W4[(k + 2) * 32 + tc];
            float4 wd = W4[(k + 3) * 32 + tc];
            #pragma unroll
            for (int i = 0; i < 4; ++i) {
                float4 x = ((const float4*)(sH + (r0 + i) * ND))[k >> 2];
                acc2[i][0] += x.x * wa.x + x.y * wb.x + x.z * wc.x + x.w * wd.x;
                acc2[i][1] += x.x * wa.y + x.y * wb.y + x.z * wc.y + x.w * wd.y;
                acc2[i][2] += x.x * wa.z + x.y * wb.z + x.z * wc.z + x.w * wd.z;
                acc2[i][3] += x.x * wa.w + x.y * wb.w + x.z * wc.w + x.w * wd.w;
            }
        }
    }

    #pragma unroll
    for (int i = 0; i < 4; ++i) {
        int n = n0 + r0 + i;
        if (n < N)
            ((float4*)(out + (size_t)n * ND))[tc] =
                make_float4(acc2[i][0], acc2[i][1], acc2[i][2], acc2[i][3]);
    }
}

// ---------------------------------------------------------------------------

extern "C" void kernel_launch(void* const* d_in, const int* in_sizes, int n_in,
                              void* d_out, int out_size)
{
    const float* node_feats = (const float*)d_in[0];
    const float* edge_feats = (const float*)d_in[1];
    const float* msg_w1     = (const float*)d_in[2];
    const float* msg_b1     = (const float*)d_in[3];
    const float* msg_w2     = (const float*)d_in[4];
    const float* msg_b2     = (const float*)d_in[5];
    const float* upd_w1     = (const float*)d_in[6];
    const float* upd_b1     = (const float*)d_in[7];
    const float* upd_w2     = (const float*)d_in[8];
    const float* upd_b2     = (const float*)d_in[9];
    const void*  edge_index = d_in[10];

    const int N = in_sizes[0] / ND;        // 50000
    const int E = in_sizes[1] / 64;        // 800000

    const int smE = (24576 + 24576) * 4;   // 196608 B
    const int smN = (32768 + 16384) * 4;   // 196608 B
    cudaFuncSetAttribute(edge_mlp_kernel, cudaFuncAttributeMaxDynamicSharedMemorySize, smE);
    cudaFuncSetAttribute(node_mlp_kernel, cudaFuncAttributeMaxDynamicSharedMemorySize, smN);

    convert_idx_kernel<<<400, 256>>>(edge_index, E);
    zero_agg_kernel<<<400, 256>>>(N * (ND / 4));

    edge_mlp_kernel<<<(E + BE - 1) / BE, 512, smE>>>(
        node_feats, edge_feats, msg_w1, msg_b1, msg_w2, msg_b2, E);

    node_mlp_kernel<<<(N + 63) / 64, 512, smN>>>(
        node_feats, upd_w1, upd_b1, upd_w2, upd_b2,
        (float*)d_out, N);
}

// round 6
// speedup vs baseline: 2.8818x; 2.8818x over previous
#include <cuda_runtime.h>
#include <cuda_fp16.h>
#include <cstdint>

// ===========================================================================
// GraphConvLayer via warp-level mma.sync (m16n8k16 fp16, fp32 accum),
// split-fp16 (hi+lo) for precision. No tcgen05 (ptxas targets base sm_103).
//
//   build_wimg : weights -> transposed, padded, fp16 hi/lo images (W2 col-perm)
//   split_f32  : node_feats / g_agg -> fp16 hi/lo images
//   tohalf     : edge_feats -> fp16 hi image
//   convert_idx: edge_index (int64/int32 auto-detect) -> g_src/g_dst
//   zero_agg   : clear fp32 scatter buffer
//   edge_mma   : 128 edges/block: GEMM1(K=192) -> lrelu -> GEMM2(K=128)
//                -> red.global.add.v4 scatter
//   node_mma   : 128 nodes/block: GEMM1(K=256, 2 chunks) -> lrelu ->
//                GEMM2(K=128) -> v4 stores
// ===========================================================================

#define MAX_N 50000
#define MAX_E 800000

__device__ float  g_agg[(size_t)MAX_N * 128];
__device__ int    g_src[MAX_E];
__device__ int    g_dst[MAX_E];
__device__ __half g_nfh[(size_t)MAX_N * 128];
__device__ __half g_nfl[(size_t)MAX_N * 128];
__device__ __half g_efh[(size_t)MAX_E * 64];
__device__ __half g_agh[(size_t)MAX_N * 128];
__device__ __half g_agl[(size_t)MAX_N * 128];
// weight images (halves): W1M(25600 hi + 25600 lo) W2M(17408x2) W1U(33792x2) W2U(17408x2)
__device__ __half g_wimg[188416];

// byte offsets into g_wimg
#define BW_W1M 0
#define BW_W2M 102400
#define BW_W1U 172032
#define BW_W2U 307200

// ---------------- helpers ----------------
__device__ __forceinline__ uint32_t smem_u32(const void* p) {
    uint32_t a;
    asm("{ .reg .u64 t; cvta.to.shared.u64 t, %1; cvt.u32.u64 %0, t; }" : "=r"(a) : "l"(p));
    return a;
}
__device__ __forceinline__ float lrelu(float v) { return v >= 0.f ? v : 0.2f * v; }
__device__ __forceinline__ uint32_t packh2(__half a, __half b) {
    __half2 h = __halves2half2(a, b);
    return *reinterpret_cast<uint32_t*>(&h);
}
__device__ __forceinline__ void ldsm4(uint32_t* r, uint32_t a) {
    asm volatile("ldmatrix.sync.aligned.m8n8.x4.shared.b16 {%0,%1,%2,%3}, [%4];"
        : "=r"(r[0]), "=r"(r[1]), "=r"(r[2]), "=r"(r[3]) : "r"(a));
}
__device__ __forceinline__ void mma16816(float* c, const uint32_t* a, uint32_t b0, uint32_t b1) {
    asm volatile("mma.sync.aligned.m16n8k16.row.col.f32.f16.f16.f32 "
        "{%0,%1,%2,%3}, {%4,%5,%6,%7}, {%8,%9}, {%0,%1,%2,%3};"
        : "+f"(c[0]), "+f"(c[1]), "+f"(c[2]), "+f"(c[3])
        : "r"(a[0]), "r"(a[1]), "r"(a[2]), "r"(a[3]), "r"(b0), "r"(b1));
}
__device__ __forceinline__ void red_add_v4(float* p, float a, float b, float c, float d) {
    asm volatile("red.global.add.v4.f32 [%0], {%1, %2, %3, %4};"
        :: "l"(p), "f"(a), "f"(b), "f"(c), "f"(d) : "memory");
}

// one k16 step of a 128x128 warp-tiled (4x4 warps, 32x32 each) GEMM.
// A row-major rows=m (ldmatrix), B row-major rows=n = N x K (ldmatrix, NO trans:
// the natural fragment of an NxK row-major tile IS the .col B fragment).
// hi/lo split: c += Ah*Bh + Ah*Bl (+ Al*Bh if doLo).
template<int AS, int BS>
__device__ __forceinline__ void gemm_step(float (&c)[2][4][4],
    uint32_t aHi, uint32_t aLo, uint32_t bHi, uint32_t bLo,
    int akb, int bkb, bool doLo, int wm, int wn, int lane)
{
    const int rs = lane & 15;
    const int hs = (lane >> 4) << 4;
    uint32_t ah[2][4], al[2][4], bh[2][4], bl[2][4];
    #pragma unroll
    for (int mt = 0; mt < 2; ++mt)
        ldsm4(ah[mt], aHi + (wm * 32 + mt * 16 + rs) * AS + akb + hs);
    if (doLo) {
        #pragma unroll
        for (int mt = 0; mt < 2; ++mt)
            ldsm4(al[mt], aLo + (wm * 32 + mt * 16 + rs) * AS + akb + hs);
    }
    #pragma unroll
    for (int nt = 0; nt < 2; ++nt) {
        ldsm4(bh[nt], bHi + (wn * 32 + nt * 16 + rs) * BS + bkb + hs);
        ldsm4(bl[nt], bLo + (wn * 32 + nt * 16 + rs) * BS + bkb + hs);
    }
    #pragma unroll
    for (int mt = 0; mt < 2; ++mt)
        #pragma unroll
        for (int nt = 0; nt < 2; ++nt) {
            mma16816(c[mt][2 * nt],     ah[mt], bh[nt][0], bh[nt][2]);
            mma16816(c[mt][2 * nt + 1], ah[mt], bh[nt][1], bh[nt][3]);
            mma16816(c[mt][2 * nt],     ah[mt], bl[nt][0], bl[nt][2]);
            mma16816(c[mt][2 * nt + 1], ah[mt], bl[nt][1], bl[nt][3]);
            if (doLo) {
                mma16816(c[mt][2 * nt],     al[mt], bh[nt][0], bh[nt][2]);
                mma16816(c[mt][2 * nt + 1], al[mt], bh[nt][1], bh[nt][3]);
            }
        }
}

// ---------------- prologue kernels ----------------
__global__ void build_wimg_kernel(const float* __restrict__ mw1, const float* __restrict__ mw2,
                                  const float* __restrict__ uw1, const float* __restrict__ uw2)
{
    int t = blockIdx.x * blockDim.x + threadIdx.x;
    if (t >= 90112) return;
    const float* src; int K, hoff, lskip; bool perm;
    if (t < 24576)      { src = mw1; K = 192; hoff = 0;      lskip = 25600; perm = false; }
    else if (t < 40960) { t -= 24576; src = mw2; K = 128; hoff = 51200;  lskip = 17408; perm = true; }
    else if (t < 73728) { t -= 40960; src = uw1; K = 256; hoff = 86016;  lskip = 33792; perm = false; }
    else                { t -= 73728; src = uw2; K = 128; hoff = 153600; lskip = 17408; perm = true; }
    int n = t / K, k = t - n * K;
    int stride = K + 8;
    float v = src[(size_t)k * 128 + n];   // W^T[n][k]
    __half h = __float2half_rn(v);
    __half l = __float2half_rn(v - __half2float(h));
    int row = n;
    if (perm) {   // logical col n -> physical row so epilogue gets 8 contiguous logical cols
        int wg = n >> 5, w = n & 31, q = w >> 3, tt = (w >> 1) & 3, r = w & 1;
        row = wg * 32 + tt * 8 + q * 2 + r;
    }
    g_wimg[hoff + row * stride + k]         = h;
    g_wimg[hoff + lskip + row * stride + k] = l;
}

__global__ void split_f32_kernel(const float* __restrict__ src_in, int which, int n2)
{
    const float* src = which ? (const float*)g_agg : src_in;
    __half* hi = which ? g_agh : g_nfh;
    __half* lo = which ? g_agl : g_nfl;
    int stride = gridDim.x * blockDim.x;
    for (int i = blockIdx.x * blockDim.x + threadIdx.x; i < n2; i += stride) {
        float2 v = ((const float2*)src)[i];
        __half h0 = __float2half_rn(v.x), h1 = __float2half_rn(v.y);
        ((uint32_t*)hi)[i] = packh2(h0, h1);
        ((uint32_t*)lo)[i] = packh2(__float2half_rn(v.x - __half2float(h0)),
                                    __float2half_rn(v.y - __half2float(h1)));
    }
}

__global__ void tohalf_kernel(const float* __restrict__ src, int n2)
{
    int stride = gridDim.x * blockDim.x;
    for (int i = blockIdx.x * blockDim.x + threadIdx.x; i < n2; i += stride) {
        float2 v = ((const float2*)src)[i];
        ((uint32_t*)g_efh)[i] = packh2(__float2half_rn(v.x), __float2half_rn(v.y));
    }
}

__global__ void convert_idx_kernel(const void* __restrict__ ei, int E)
{
    const int* p32 = (const int*)ei;
    int s = 0;
    #pragma unroll
    for (int i = 0; i < 16; ++i) s |= p32[2 * i + 1];
    const bool is64 = (s == 0);
    const int stride = gridDim.x * blockDim.x;
    if (is64) {
        const long long* p = (const long long*)ei;
        for (int i = blockIdx.x * blockDim.x + threadIdx.x; i < E; i += stride) {
            g_src[i] = (int)p[i];
            g_dst[i] = (int)p[(size_t)E + i];
        }
    } else {
        for (int i = blockIdx.x * blockDim.x + threadIdx.x; i < E; i += stride) {
            g_src[i] = p32[i];
            g_dst[i] = p32[(size_t)E + i];
        }
    }
}

__global__ void zero_agg_kernel(int n4) {
    float4 z = make_float4(0.f, 0.f, 0.f, 0.f);
    float4* p = (float4*)g_agg;
    for (int i = blockIdx.x * blockDim.x + threadIdx.x; i < n4; i += gridDim.x * blockDim.x)
        p[i] = z;
}

// ---------------- edge kernel smem layout (bytes) ----------------
#define E_XH  0        // X hi 128x400 (later H hi, stride 272)
#define E_XL  51200    // X lo          (later H lo)
#define E_WH  102400   // W1 hi 51200 | later W2 hi 34816
#define E_W1L 153600   // W1 lo (contiguous after hi)
#define E_W2L 137216   // W2 lo (= E_WH + 34816)
#define E_SRC 204800
#define E_DST 205312
#define E_SB1 205824
#define E_SB2 206336
#define DYN_SZ 206848

__global__ __launch_bounds__(512, 1)
void edge_mma_kernel(const float* __restrict__ b1g, const float* __restrict__ b2g, int E)
{
    extern __shared__ char smx[];
    const uint32_t sb = smem_u32(smx);
    int*   s_src = (int*)(smx + E_SRC);
    int*   s_dst = (int*)(smx + E_DST);
    float* sb1   = (float*)(smx + E_SB1);
    float* sb2   = (float*)(smx + E_SB2);
    const int tid = threadIdx.x, lane = tid & 31, wid = tid >> 5;
    const int wm = wid & 3, wn = wid >> 2;
    const int e0 = blockIdx.x * 128;

    if (tid < 128) {
        int e = e0 + tid;
        s_src[tid] = (e < E) ? g_src[e] : -1;
        s_dst[tid] = (e < E) ? g_dst[e] : 0;
    } else if (tid < 256) sb1[tid - 128] = b1g[tid - 128];
    else if (tid < 384)   sb2[tid - 256] = b2g[tid - 256];
    {   // stage W1^T hi+lo (102400 B contiguous)
        const uint4* s = (const uint4*)((const char*)g_wimg + BW_W1M);
        uint4* d = (uint4*)(smx + E_WH);
        for (int i = tid; i < 6400; i += 512) d[i] = s[i];
    }
    __syncthreads();

    // gather X: per row 16 uint4 node-hi, 16 node-lo, 8 edge-hi
    for (int t = tid; t < 128 * 40; t += 512) {
        int row = t / 40, ch = t - row * 40;
        if (ch < 16) {
            int dn = s_dst[row];
            *(uint4*)(smx + E_XH + row * 400 + ch * 16) =
                ((const uint4*)(g_nfh + (size_t)dn * 128))[ch];
        } else if (ch < 32) {
            int dn = s_dst[row];
            *(uint4*)(smx + E_XL + row * 400 + (ch - 16) * 16) =
                ((const uint4*)(g_nfl + (size_t)dn * 128))[ch - 16];
        } else {
            *(uint4*)(smx + E_XH + row * 400 + 256 + (ch - 32) * 16) =
                ((const uint4*)(g_efh + (size_t)(e0 + row) * 64))[ch - 32];
        }
    }
    __syncthreads();

    // GEMM1: K=192 (ksteps 0..7 node cols w/ A-lo; 8..11 edge cols hi-only)
    float c[2][4][4];
    #pragma unroll
    for (int i = 0; i < 2; ++i)
        #pragma unroll
        for (int j = 0; j < 4; ++j)
            #pragma unroll
            for (int r = 0; r < 4; ++r) c[i][j][r] = 0.f;
    #pragma unroll
    for (int k = 0; k < 12; ++k)
        gemm_step<400, 400>(c, sb + E_XH, sb + E_XL, sb + E_WH, sb + E_W1L,
                            k * 32, k * 32, k < 8, wm, wn, lane);
    __syncthreads();

    // epilogue1: bias+lrelu, split fp16, write H (stride 272) + stage W2
    #pragma unroll
    for (int mt = 0; mt < 2; ++mt)
        #pragma unroll
        for (int nt = 0; nt < 4; ++nt) {
            int r0  = wm * 32 + mt * 16 + (lane >> 2);
            int col = wn * 32 + nt * 8 + (lane & 3) * 2;
            float ba = sb1[col], bb = sb1[col + 1];
            float f0 = lrelu(c[mt][nt][0] + ba), f1 = lrelu(c[mt][nt][1] + bb);
            float f2 = lrelu(c[mt][nt][2] + ba), f3 = lrelu(c[mt][nt][3] + bb);
            __half h0 = __float2half_rn(f0), h1 = __float2half_rn(f1);
            __half h2 = __float2half_rn(f2), h3 = __float2half_rn(f3);
            *(uint32_t*)(smx + E_XH + r0 * 272 + col * 2)       = packh2(h0, h1);
            *(uint32_t*)(smx + E_XH + (r0 + 8) * 272 + col * 2) = packh2(h2, h3);
            *(uint32_t*)(smx + E_XL + r0 * 272 + col * 2) =
                packh2(__float2half_rn(f0 - __half2float(h0)), __float2half_rn(f1 - __half2float(h1)));
            *(uint32_t*)(smx + E_XL + (r0 + 8) * 272 + col * 2) =
                packh2(__float2half_rn(f2 - __half2float(h2)), __float2half_rn(f3 - __half2float(h3)));
        }
    {
        const uint4* s = (const uint4*)((const char*)g_wimg + BW_W2M);
        uint4* d = (uint4*)(smx + E_WH);
        for (int i = tid; i < 4352; i += 512) d[i] = s[i];
    }
    __syncthreads();

    // GEMM2: K=128
    #pragma unroll
    for (int i = 0; i < 2; ++i)
        #pragma unroll
        for (int j = 0; j < 4; ++j)
            #pragma unroll
            for (int r = 0; r < 4; ++r) c[i][j][r] = 0.f;
    #pragma unroll
    for (int k = 0; k < 8; ++k)
        gemm_step<272, 272>(c, sb + E_XH, sb + E_XL, sb + E_WH, sb + E_W2L,
                            k * 32, k * 32, true, wm, wn, lane);

    // epilogue2: bias + vector scatter-add (W2 perm gives 8 contiguous cols/thread)
    {
        const int q = lane & 3;
        const int Lb = wn * 32 + q * 8;
        float c0 = sb2[Lb],     c1 = sb2[Lb + 1], c2 = sb2[Lb + 2], c3 = sb2[Lb + 3];
        float c4 = sb2[Lb + 4], c5 = sb2[Lb + 5], c6 = sb2[Lb + 6], c7 = sb2[Lb + 7];
        #pragma unroll
        for (int mt = 0; mt < 2; ++mt) {
            int r = wm * 32 + mt * 16 + (lane >> 2);
            int s0 = s_src[r], s1 = s_src[r + 8];
            if (s0 >= 0) {
                float* p = g_agg + (size_t)s0 * 128 + Lb;
                red_add_v4(p,     c[mt][0][0] + c0, c[mt][0][1] + c1, c[mt][1][0] + c2, c[mt][1][1] + c3);
                red_add_v4(p + 4, c[mt][2][0] + c4, c[mt][2][1] + c5, c[mt][3][0] + c6, c[mt][3][1] + c7);
            }
            if (s1 >= 0) {
                float* p = g_agg + (size_t)s1 * 128 + Lb;
                red_add_v4(p,     c[mt][0][2] + c0, c[mt][0][3] + c1, c[mt][1][2] + c2, c[mt][1][3] + c3);
                red_add_v4(p + 4, c[mt][2][2] + c4, c[mt][2][3] + c5, c[mt][3][2] + c6, c[mt][3][3] + c7);
            }
        }
    }
}

// ---------------- node kernel smem layout (bytes) ----------------
#define N_WH  0        // W1U hi 67584 | later W2U hi 34816
#define N_W1L 67584
#define N_W2L 34816
#define N_XH  135168   // X chunk hi 34816 (later H hi)
#define N_XL  169984
#define N_SB1 204800
#define N_SB2 205312

__global__ __launch_bounds__(512, 1)
void node_mma_kernel(const float* __restrict__ b1g, const float* __restrict__ b2g,
                     float* __restrict__ out, int N)
{
    extern __shared__ char smx[];
    const uint32_t sb = smem_u32(smx);
    float* sb1 = (float*)(smx + N_SB1);
    float* sb2 = (float*)(smx + N_SB2);
    const int tid = threadIdx.x, lane = tid & 31, wid = tid >> 5;
    const int wm = wid & 3, wn = wid >> 2;
    const int n0 = blockIdx.x * 128;

    if (tid < 128)      sb1[tid] = b1g[tid];
    else if (tid < 256) sb2[tid - 128] = b2g[tid - 128];
    {   // stage W1U^T hi+lo (135168 B)
        const uint4* s = (const uint4*)((const char*)g_wimg + BW_W1U);
        uint4* d = (uint4*)(smx + N_WH);
        for (int i = tid; i < 8448; i += 512) d[i] = s[i];
    }
    // X chunk0: node_feats hi/lo
    for (int t = tid; t < 128 * 32; t += 512) {
        int row = t >> 5, ch = t & 31;
        int n = n0 + row; if (n >= N) n = N - 1;
        if (ch < 16)
            *(uint4*)(smx + N_XH + row * 272 + ch * 16) = ((const uint4*)(g_nfh + (size_t)n * 128))[ch];
        else
            *(uint4*)(smx + N_XL + row * 272 + (ch - 16) * 16) = ((const uint4*)(g_nfl + (size_t)n * 128))[ch - 16];
    }
    __syncthreads();

    float c[2][4][4];
    #pragma unroll
    for (int i = 0; i < 2; ++i)
        #pragma unroll
        for (int j = 0; j < 4; ++j)
            #pragma unroll
            for (int r = 0; r < 4; ++r) c[i][j][r] = 0.f;
    #pragma unroll
    for (int k = 0; k < 8; ++k)
        gemm_step<272, 528>(c, sb + N_XH, sb + N_XL, sb + N_WH, sb + N_W1L,
                            k * 32, k * 32, true, wm, wn, lane);
    __syncthreads();

    // X chunk1: g_agg hi/lo
    for (int t = tid; t < 128 * 32; t += 512) {
        int row = t >> 5, ch = t & 31;
        int n = n0 + row; if (n >= N) n = N - 1;
        if (ch < 16)
            *(uint4*)(smx + N_XH + row * 272 + ch * 16) = ((const uint4*)(g_agh + (size_t)n * 128))[ch];
        else
            *(uint4*)(smx + N_XL + row * 272 + (ch - 16) * 16) = ((const uint4*)(g_agl + (size_t)n * 128))[ch - 16];
    }
    __syncthreads();
    #pragma unroll
    for (int k = 0; k < 8; ++k)
        gemm_step<272, 528>(c, sb + N_XH, sb + N_XL, sb + N_WH, sb + N_W1L,
                            k * 32, 256 + k * 32, true, wm, wn, lane);
    __syncthreads();

    // epilogue1 + stage W2U
    #pragma unroll
    for (int mt = 0; mt < 2; ++mt)
        #pragma unroll
        for (int nt = 0; nt < 4; ++nt) {
            int r0  = wm * 32 + mt * 16 + (lane >> 2);
            int col = wn * 32 + nt * 8 + (lane & 3) * 2;
            float ba = sb1[col], bb = sb1[col + 1];
            float f0 = lrelu(c[mt][nt][0] + ba), f1 = lrelu(c[mt][nt][1] + bb);
            float f2 = lrelu(c[mt][nt][2] + ba), f3 = lrelu(c[mt][nt][3] + bb);
            __half h0 = __float2half_rn(f0), h1 = __float2half_rn(f1);
            __half h2 = __float2half_rn(f2), h3 = __float2half_rn(f3);
            *(uint32_t*)(smx + N_XH + r0 * 272 + col * 2)       = packh2(h0, h1);
            *(uint32_t*)(smx + N_XH + (r0 + 8) * 272 + col * 2) = packh2(h2, h3);
            *(uint32_t*)(smx + N_XL + r0 * 272 + col * 2) =
                packh2(__float2half_rn(f0 - __half2float(h0)), __float2half_rn(f1 - __half2float(h1)));
            *(uint32_t*)(smx + N_XL + (r0 + 8) * 272 + col * 2) =
                packh2(__float2half_rn(f2 - __half2float(h2)), __float2half_rn(f3 - __half2float(h3)));
        }
    {
        const uint4* s = (const uint4*)((const char*)g_wimg + BW_W2U);
        uint4* d = (uint4*)(smx + N_WH);
        for (int i = tid; i < 4352; i += 512) d[i] = s[i];
    }
    __syncthreads();

    // GEMM2: K=128
    #pragma unroll
    for (int i = 0; i < 2; ++i)
        #pragma unroll
        for (int j = 0; j < 4; ++j)
            #pragma unroll
            for (int r = 0; r < 4; ++r) c[i][j][r] = 0.f;
    #pragma unroll
    for (int k = 0; k < 8; ++k)
        gemm_step<272, 272>(c, sb + N_XH, sb + N_XL, sb + N_WH, sb + N_W2L,
                            k * 32, k * 32, true, wm, wn, lane);

    // epilogue2: bias + v4 stores
    {
        const int q = lane & 3;
        const int Lb = wn * 32 + q * 8;
        float c0 = sb2[Lb],     c1 = sb2[Lb + 1], c2 = sb2[Lb + 2], c3 = sb2[Lb + 3];
        float c4 = sb2[Lb + 4], c5 = sb2[Lb + 5], c6 = sb2[Lb + 6], c7 = sb2[Lb + 7];
        #pragma unroll
        for (int mt = 0; mt < 2; ++mt) {
            int r = wm * 32 + mt * 16 + (lane >> 2);
            int nA = n0 + r, nB = n0 + r + 8;
            if (nA < N) {
                float4* p = (float4*)(out + (size_t)nA * 128 + Lb);
                p[0] = make_float4(c[mt][0][0] + c0, c[mt][0][1] + c1, c[mt][1][0] + c2, c[mt][1][1] + c3);
                p[1] = make_float4(c[mt][2][0] + c4, c[mt][2][1] + c5, c[mt][3][0] + c6, c[mt][3][1] + c7);
            }
            if (nB < N) {
                float4* p = (float4*)(out + (size_t)nB * 128 + Lb);
                p[0] = make_float4(c[mt][0][2] + c0, c[mt][0][3] + c1, c[mt][1][2] + c2, c[mt][1][3] + c3);
                p[1] = make_float4(c[mt][2][2] + c4, c[mt][2][3] + c5, c[mt][3][2] + c6, c[mt][3][3] + c7);
            }
        }
    }
}

// ---------------------------------------------------------------------------

extern "C" void kernel_launch(void* const* d_in, const int* in_sizes, int n_in,
                              void* d_out, int out_size)
{
    const float* node_feats = (const float*)d_in[0];
    const float* edge_feats = (const float*)d_in[1];
    const float* msg_w1     = (const float*)d_in[2];
    const float* msg_b1     = (const float*)d_in[3];
    const float* msg_w2     = (const float*)d_in[4];
    const float* msg_b2     = (const float*)d_in[5];
    const float* upd_w1     = (const float*)d_in[6];
    const float* upd_b1     = (const float*)d_in[7];
    const float* upd_w2     = (const float*)d_in[8];
    const float* upd_b2     = (const float*)d_in[9];
    const void*  edge_index = d_in[10];

    const int N = in_sizes[0] / 128;   // 50000
    const int E = in_sizes[1] / 64;    // 800000

    cudaFuncSetAttribute(edge_mma_kernel, cudaFuncAttributeMaxDynamicSharedMemorySize, DYN_SZ);
    cudaFuncSetAttribute(node_mma_kernel, cudaFuncAttributeMaxDynamicSharedMemorySize, DYN_SZ);

    build_wimg_kernel<<<352, 256>>>(msg_w1, msg_w2, upd_w1, upd_w2);
    split_f32_kernel<<<1024, 256>>>(node_feats, 0, N * 64);
    tohalf_kernel<<<2048, 256>>>(edge_feats, E * 32);
    convert_idx_kernel<<<400, 256>>>(edge_index, E);
    zero_agg_kernel<<<400, 256>>>(N * 32);

    edge_mma_kernel<<<(E + 127) / 128, 512, DYN_SZ>>>(msg_b1, msg_b2, E);

    split_f32_kernel<<<1024, 256>>>(nullptr, 1, N * 64);

    node_mma_kernel<<<(N + 127) / 128, 512, DYN_SZ>>>(upd_b1, upd_b2, (float*)d_out, N);
}

// round 7
// speedup vs baseline: 4.9983x; 1.7344x over previous
#include <cuda_runtime.h>
#include <cuda_fp16.h>
#include <cstdint>

// ===========================================================================
// GraphConvLayer via warp-level mma.sync (m16n8k16 fp16, fp32 accum).
// v2: persistent edge blocks (weights staged once), 2-term split in edge
// kernel (Ah*Bh + Ah*Bl), fused fp32->fp16 conversions in gathers.
//   node kernel keeps full 3-term split for the final output precision.
// ===========================================================================

#define MAX_N 50000
#define MAX_E 800000

__device__ float  g_agg[(size_t)MAX_N * 128];
__device__ int    g_src[MAX_E];
__device__ int    g_dst[MAX_E];
__device__ __half g_nfh[(size_t)MAX_N * 128];
__device__ __half g_nfl[(size_t)MAX_N * 128];
// weight images (halves): W1M(25600 hi + 25600 lo) W2M(17408x2) W1U(33792x2) W2U(17408x2)
__device__ __half g_wimg[188416];

// byte offsets into g_wimg
#define BW_W1M 0
#define BW_W2M 102400
#define BW_W1U 172032
#define BW_W2U 307200

// ---------------- helpers ----------------
__device__ __forceinline__ uint32_t smem_u32(const void* p) {
    uint32_t a;
    asm("{ .reg .u64 t; cvta.to.shared.u64 t, %1; cvt.u32.u64 %0, t; }" : "=r"(a) : "l"(p));
    return a;
}
__device__ __forceinline__ float lrelu(float v) { return v >= 0.f ? v : 0.2f * v; }
__device__ __forceinline__ uint32_t packh2(__half a, __half b) {
    __half2 h = __halves2half2(a, b);
    return *reinterpret_cast<uint32_t*>(&h);
}
__device__ __forceinline__ void ldsm4(uint32_t* r, uint32_t a) {
    asm volatile("ldmatrix.sync.aligned.m8n8.x4.shared.b16 {%0,%1,%2,%3}, [%4];"
        : "=r"(r[0]), "=r"(r[1]), "=r"(r[2]), "=r"(r[3]) : "r"(a));
}
__device__ __forceinline__ void mma16816(float* c, const uint32_t* a, uint32_t b0, uint32_t b1) {
    asm volatile("mma.sync.aligned.m16n8k16.row.col.f32.f16.f16.f32 "
        "{%0,%1,%2,%3}, {%4,%5,%6,%7}, {%8,%9}, {%0,%1,%2,%3};"
        : "+f"(c[0]), "+f"(c[1]), "+f"(c[2]), "+f"(c[3])
        : "r"(a[0]), "r"(a[1]), "r"(a[2]), "r"(a[3]), "r"(b0), "r"(b1));
}
__device__ __forceinline__ void red_add_v4(float* p, float a, float b, float c, float d) {
    asm volatile("red.global.add.v4.f32 [%0], {%1, %2, %3, %4};"
        :: "l"(p), "f"(a), "f"(b), "f"(c), "f"(d) : "memory");
}

// 2-term k16 step: c += Ah*Bh + Ah*Bl. A row-major rows=m, B = N x K row-major.
template<int AS, int BS>
__device__ __forceinline__ void gemm_step2(float (&c)[2][4][4],
    uint32_t aHi, uint32_t bHi, uint32_t bLo,
    int akb, int bkb, int wm, int wn, int lane)
{
    const int rs = lane & 15;
    const int hs = (lane >> 4) << 4;
    uint32_t ah[2][4], bh[2][4], bl[2][4];
    #pragma unroll
    for (int mt = 0; mt < 2; ++mt)
        ldsm4(ah[mt], aHi + (wm * 32 + mt * 16 + rs) * AS + akb + hs);
    #pragma unroll
    for (int nt = 0; nt < 2; ++nt) {
        ldsm4(bh[nt], bHi + (wn * 32 + nt * 16 + rs) * BS + bkb + hs);
        ldsm4(bl[nt], bLo + (wn * 32 + nt * 16 + rs) * BS + bkb + hs);
    }
    #pragma unroll
    for (int mt = 0; mt < 2; ++mt)
        #pragma unroll
        for (int nt = 0; nt < 2; ++nt) {
            mma16816(c[mt][2 * nt],     ah[mt], bh[nt][0], bh[nt][2]);
            mma16816(c[mt][2 * nt + 1], ah[mt], bh[nt][1], bh[nt][3]);
            mma16816(c[mt][2 * nt],     ah[mt], bl[nt][0], bl[nt][2]);
            mma16816(c[mt][2 * nt + 1], ah[mt], bl[nt][1], bl[nt][3]);
        }
}

// 3-term k16 step (adds Al*Bh) — node kernel.
template<int AS, int BS>
__device__ __forceinline__ void gemm_step3(float (&c)[2][4][4],
    uint32_t aHi, uint32_t aLo, uint32_t bHi, uint32_t bLo,
    int akb, int bkb, int wm, int wn, int lane)
{
    const int rs = lane & 15;
    const int hs = (lane >> 4) << 4;
    uint32_t ah[2][4], al[2][4], bh[2][4], bl[2][4];
    #pragma unroll
    for (int mt = 0; mt < 2; ++mt) {
        ldsm4(ah[mt], aHi + (wm * 32 + mt * 16 + rs) * AS + akb + hs);
        ldsm4(al[mt], aLo + (wm * 32 + mt * 16 + rs) * AS + akb + hs);
    }
    #pragma unroll
    for (int nt = 0; nt < 2; ++nt) {
        ldsm4(bh[nt], bHi + (wn * 32 + nt * 16 + rs) * BS + bkb + hs);
        ldsm4(bl[nt], bLo + (wn * 32 + nt * 16 + rs) * BS + bkb + hs);
    }
    #pragma unroll
    for (int mt = 0; mt < 2; ++mt)
        #pragma unroll
        for (int nt = 0; nt < 2; ++nt) {
            mma16816(c[mt][2 * nt],     ah[mt], bh[nt][0], bh[nt][2]);
            mma16816(c[mt][2 * nt + 1], ah[mt], bh[nt][1], bh[nt][3]);
            mma16816(c[mt][2 * nt],     ah[mt], bl[nt][0], bl[nt][2]);
            mma16816(c[mt][2 * nt + 1], ah[mt], bl[nt][1], bl[nt][3]);
            mma16816(c[mt][2 * nt],     al[mt], bh[nt][0], bh[nt][2]);
            mma16816(c[mt][2 * nt + 1], al[mt], bh[nt][1], bh[nt][3]);
        }
}

__device__ __forceinline__ void splitpack8(float4 v0, float4 v1, uint4& hi, uint4& lo) {
    float f[8] = {v0.x, v0.y, v0.z, v0.w, v1.x, v1.y, v1.z, v1.w};
    uint32_t hw[4], lw[4];
    #pragma unroll
    for (int j = 0; j < 4; ++j) {
        __half h0 = __float2half_rn(f[2 * j]), h1 = __float2half_rn(f[2 * j + 1]);
        hw[j] = packh2(h0, h1);
        lw[j] = packh2(__float2half_rn(f[2 * j] - __half2float(h0)),
                       __float2half_rn(f[2 * j + 1] - __half2float(h1)));
    }
    hi = make_uint4(hw[0], hw[1], hw[2], hw[3]);
    lo = make_uint4(lw[0], lw[1], lw[2], lw[3]);
}

// ---------------- prologue kernels ----------------
__global__ void build_wimg_kernel(const float* __restrict__ mw1, const float* __restrict__ mw2,
                                  const float* __restrict__ uw1, const float* __restrict__ uw2)
{
    int t = blockIdx.x * blockDim.x + threadIdx.x;
    if (t >= 90112) return;
    const float* src; int K, hoff, lskip; bool perm;
    if (t < 24576)      { src = mw1; K = 192; hoff = 0;      lskip = 25600; perm = false; }
    else if (t < 40960) { t -= 24576; src = mw2; K = 128; hoff = 51200;  lskip = 17408; perm = true; }
    else if (t < 73728) { t -= 40960; src = uw1; K = 256; hoff = 86016;  lskip = 33792; perm = false; }
    else                { t -= 73728; src = uw2; K = 128; hoff = 153600; lskip = 17408; perm = true; }
    int n = t / K, k = t - n * K;
    int stride = K + 8;
    float v = src[(size_t)k * 128 + n];   // W^T[n][k]
    __half h = __float2half_rn(v);
    __half l = __float2half_rn(v - __half2float(h));
    int row = n;
    if (perm) {   // logical col n -> physical row so epilogue gets 8 contiguous logical cols
        int wg = n >> 5, w = n & 31, q = w >> 3, tt = (w >> 1) & 3, r = w & 1;
        row = wg * 32 + tt * 8 + q * 2 + r;
    }
    g_wimg[hoff + row * stride + k]         = h;
    g_wimg[hoff + lskip + row * stride + k] = l;
}

__global__ void split_nf_kernel(const float* __restrict__ src, int n2)
{
    int stride = gridDim.x * blockDim.x;
    for (int i = blockIdx.x * blockDim.x + threadIdx.x; i < n2; i += stride) {
        float2 v = ((const float2*)src)[i];
        __half h0 = __float2half_rn(v.x), h1 = __float2half_rn(v.y);
        ((uint32_t*)g_nfh)[i] = packh2(h0, h1);
        ((uint32_t*)g_nfl)[i] = packh2(__float2half_rn(v.x - __half2float(h0)),
                                       __float2half_rn(v.y - __half2float(h1)));
    }
}

__global__ void convert_idx_kernel(const void* __restrict__ ei, int E)
{
    const int* p32 = (const int*)ei;
    int s = 0;
    #pragma unroll
    for (int i = 0; i < 16; ++i) s |= p32[2 * i + 1];
    const bool is64 = (s == 0);
    const int stride = gridDim.x * blockDim.x;
    if (is64) {
        const long long* p = (const long long*)ei;
        for (int i = blockIdx.x * blockDim.x + threadIdx.x; i < E; i += stride) {
            g_src[i] = (int)p[i];
            g_dst[i] = (int)p[(size_t)E + i];
        }
    } else {
        for (int i = blockIdx.x * blockDim.x + threadIdx.x; i < E; i += stride) {
            g_src[i] = p32[i];
            g_dst[i] = p32[(size_t)E + i];
        }
    }
}

__global__ void zero_agg_kernel(int n4) {
    float4 z = make_float4(0.f, 0.f, 0.f, 0.f);
    float4* p = (float4*)g_agg;
    for (int i = blockIdx.x * blockDim.x + threadIdx.x; i < n4; i += gridDim.x * blockDim.x)
        p[i] = z;
}

// ---------------- edge kernel smem layout (bytes) ----------------
// W1 hi+lo resident 102400 | W2 hi+lo resident 69632 | X hi 51200 (H overlays)
#define E_W1  0
#define E_W2  102400
#define E_W2L 137216
#define E_X   172032
#define E_SRC 223232
#define E_DST 223744
#define E_SB1 224256
#define E_SB2 224768
#define E_DYN 225280

__global__ __launch_bounds__(512, 1)
void edge_mma_kernel(const float* __restrict__ edge_feats,
                     const float* __restrict__ b1g, const float* __restrict__ b2g,
                     int E, int nTiles)
{
    extern __shared__ char smx[];
    const uint32_t sb = smem_u32(smx);
    int*   s_src = (int*)(smx + E_SRC);
    int*   s_dst = (int*)(smx + E_DST);
    float* sb1   = (float*)(smx + E_SB1);
    float* sb2   = (float*)(smx + E_SB2);
    const int tid = threadIdx.x, lane = tid & 31, wid = tid >> 5;
    const int wm = wid & 3, wn = wid >> 2;

    if (tid < 128)      sb1[tid] = b1g[tid];
    else if (tid < 256) sb2[tid - 128] = b2g[tid - 128];
    {   // stage W1 hi+lo (102400 B) + W2 hi+lo (69632 B) ONCE per block
        const uint4* s1 = (const uint4*)((const char*)g_wimg + BW_W1M);
        uint4* d1 = (uint4*)(smx + E_W1);
        for (int i = tid; i < 6400; i += 512) d1[i] = s1[i];
        const uint4* s2 = (const uint4*)((const char*)g_wimg + BW_W2M);
        uint4* d2 = (uint4*)(smx + E_W2);
        for (int i = tid; i < 4352; i += 512) d2[i] = s2[i];
    }

    for (int tile = blockIdx.x; tile < nTiles; tile += gridDim.x) {
        const int e0 = tile * 128;
        __syncthreads();                 // prior tile fully consumed s_src / X region
        if (tid < 128) {
            int e = e0 + tid;
            s_src[tid] = (e < E) ? g_src[e] : -1;
            s_dst[tid] = (e < E) ? g_dst[e] : 0;
        }
        __syncthreads();

        // gather X hi: 16 node uint4 + 8 edge uint4 (fp32->fp16 fused) per row
        for (int t = tid; t < 128 * 24; t += 512) {
            int row = t / 24, ch = t - row * 24;
            if (ch < 16) {
                int dn = s_dst[row];
                *(uint4*)(smx + E_X + row * 400 + ch * 16) =
                    ((const uint4*)(g_nfh + (size_t)dn * 128))[ch];
            } else {
                const float4* bp = (const float4*)(edge_feats + (size_t)(e0 + row) * 64 + (ch - 16) * 8);
                float4 v0 = bp[0], v1 = bp[1];
                uint32_t w0 = packh2(__float2half_rn(v0.x), __float2half_rn(v0.y));
                uint32_t w1 = packh2(__float2half_rn(v0.z), __float2half_rn(v0.w));
                uint32_t w2 = packh2(__float2half_rn(v1.x), __float2half_rn(v1.y));
                uint32_t w3 = packh2(__float2half_rn(v1.z), __float2half_rn(v1.w));
                *(uint4*)(smx + E_X + row * 400 + 256 + (ch - 16) * 16) = make_uint4(w0, w1, w2, w3);
            }
        }
        __syncthreads();

        // GEMM1: K=192, 2-term
        float c[2][4][4];
        #pragma unroll
        for (int i = 0; i < 2; ++i)
            #pragma unroll
            for (int j = 0; j < 4; ++j)
                #pragma unroll
                for (int r = 0; r < 4; ++r) c[i][j][r] = 0.f;
        #pragma unroll
        for (int k = 0; k < 12; ++k)
            gemm_step2<400, 400>(c, sb + E_X, sb + E_W1, sb + E_W1 + 51200,
                                 k * 32, k * 32, wm, wn, lane);
        __syncthreads();                 // all reads of X done before H overlay

        // epilogue1: bias+lrelu -> H hi (stride 272) over X region
        #pragma unroll
        for (int mt = 0; mt < 2; ++mt)
            #pragma unroll
            for (int nt = 0; nt < 4; ++nt) {
                int r0  = wm * 32 + mt * 16 + (lane >> 2);
                int col = wn * 32 + nt * 8 + (lane & 3) * 2;
                float ba = sb1[col], bb = sb1[col + 1];
                float f0 = lrelu(c[mt][nt][0] + ba), f1 = lrelu(c[mt][nt][1] + bb);
                float f2 = lrelu(c[mt][nt][2] + ba), f3 = lrelu(c[mt][nt][3] + bb);
                *(uint32_t*)(smx + E_X + r0 * 272 + col * 2) =
                    packh2(__float2half_rn(f0), __float2half_rn(f1));
                *(uint32_t*)(smx + E_X + (r0 + 8) * 272 + col * 2) =
                    packh2(__float2half_rn(f2), __float2half_rn(f3));
            }
        __syncthreads();

        // GEMM2: K=128, 2-term (H hi only)
        #pragma unroll
        for (int i = 0; i < 2; ++i)
            #pragma unroll
            for (int j = 0; j < 4; ++j)
                #pragma unroll
                for (int r = 0; r < 4; ++r) c[i][j][r] = 0.f;
        #pragma unroll
        for (int k = 0; k < 8; ++k)
            gemm_step2<272, 272>(c, sb + E_X, sb + E_W2, sb + E_W2L,
                                 k * 32, k * 32, wm, wn, lane);

        // epilogue2: bias + vector scatter-add (W2 col-perm -> 8 contiguous cols)
        {
            const int q = lane & 3;
            const int Lb = wn * 32 + q * 8;
            float c0 = sb2[Lb],     c1 = sb2[Lb + 1], c2 = sb2[Lb + 2], c3 = sb2[Lb + 3];
            float c4 = sb2[Lb + 4], c5 = sb2[Lb + 5], c6 = sb2[Lb + 6], c7 = sb2[Lb + 7];
            #pragma unroll
            for (int mt = 0; mt < 2; ++mt) {
                int r = wm * 32 + mt * 16 + (lane >> 2);
                int s0 = s_src[r], s1 = s_src[r + 8];
                if (s0 >= 0) {
                    float* p = g_agg + (size_t)s0 * 128 + Lb;
                    red_add_v4(p,     c[mt][0][0] + c0, c[mt][0][1] + c1, c[mt][1][0] + c2, c[mt][1][1] + c3);
                    red_add_v4(p + 4, c[mt][2][0] + c4, c[mt][2][1] + c5, c[mt][3][0] + c6, c[mt][3][1] + c7);
                }
                if (s1 >= 0) {
                    float* p = g_agg + (size_t)s1 * 128 + Lb;
                    red_add_v4(p,     c[mt][0][2] + c0, c[mt][0][3] + c1, c[mt][1][2] + c2, c[mt][1][3] + c3);
                    red_add_v4(p + 4, c[mt][2][2] + c4, c[mt][2][3] + c5, c[mt][3][2] + c6, c[mt][3][3] + c7);
                }
            }
        }
    }
}

// ---------------- node kernel smem layout (bytes) ----------------
#define N_WH  0        // W1U hi 67584 | later W2U hi 34816
#define N_W1L 67584
#define N_W2L 34816
#define N_XH  135168   // X chunk hi 34816 (later H hi)
#define N_XL  169984
#define N_SB1 204800
#define N_SB2 205312
#define N_DYN 206848

__global__ __launch_bounds__(512, 1)
void node_mma_kernel(const float* __restrict__ b1g, const float* __restrict__ b2g,
                     float* __restrict__ out, int N)
{
    extern __shared__ char smx[];
    const uint32_t sb = smem_u32(smx);
    float* sb1 = (float*)(smx + N_SB1);
    float* sb2 = (float*)(smx + N_SB2);
    const int tid = threadIdx.x, lane = tid & 31, wid = tid >> 5;
    const int wm = wid & 3, wn = wid >> 2;
    const int n0 = blockIdx.x * 128;

    if (tid < 128)      sb1[tid] = b1g[tid];
    else if (tid < 256) sb2[tid - 128] = b2g[tid - 128];
    {   // stage W1U^T hi+lo (135168 B)
        const uint4* s = (const uint4*)((const char*)g_wimg + BW_W1U);
        uint4* d = (uint4*)(smx + N_WH);
        for (int i = tid; i < 8448; i += 512) d[i] = s[i];
    }
    // X chunk0: node_feats hi/lo from precomputed images
    for (int t = tid; t < 128 * 32; t += 512) {
        int row = t >> 5, ch = t & 31;
        int n = n0 + row; if (n >= N) n = N - 1;
        if (ch < 16)
            *(uint4*)(smx + N_XH + row * 272 + ch * 16) = ((const uint4*)(g_nfh + (size_t)n * 128))[ch];
        else
            *(uint4*)(smx + N_XL + row * 272 + (ch - 16) * 16) = ((const uint4*)(g_nfl + (size_t)n * 128))[ch - 16];
    }
    __syncthreads();

    float c[2][4][4];
    #pragma unroll
    for (int i = 0; i < 2; ++i)
        #pragma unroll
        for (int j = 0; j < 4; ++j)
            #pragma unroll
            for (int r = 0; r < 4; ++r) c[i][j][r] = 0.f;
    #pragma unroll
    for (int k = 0; k < 8; ++k)
        gemm_step3<272, 528>(c, sb + N_XH, sb + N_XL, sb + N_WH, sb + N_W1L,
                             k * 32, k * 32, wm, wn, lane);
    __syncthreads();

    // X chunk1: g_agg fp32 -> hi/lo split fused here (no prologue pass)
    for (int t = tid; t < 128 * 16; t += 512) {
        int row = t >> 4, ch = t & 15;
        int n = n0 + row; if (n >= N) n = N - 1;
        const float4* bp = (const float4*)(g_agg + (size_t)n * 128 + ch * 8);
        uint4 hi, lo;
        splitpack8(bp[0], bp[1], hi, lo);
        *(uint4*)(smx + N_XH + row * 272 + ch * 16) = hi;
        *(uint4*)(smx + N_XL + row * 272 + ch * 16) = lo;
    }
    __syncthreads();
    #pragma unroll
    for (int k = 0; k < 8; ++k)
        gemm_step3<272, 528>(c, sb + N_XH, sb + N_XL, sb + N_WH, sb + N_W1L,
                             k * 32, 256 + k * 32, wm, wn, lane);
    __syncthreads();

    // epilogue1 + stage W2U
    #pragma unroll
    for (int mt = 0; mt < 2; ++mt)
        #pragma unroll
        for (int nt = 0; nt < 4; ++nt) {
            int r0  = wm * 32 + mt * 16 + (lane >> 2);
            int col = wn * 32 + nt * 8 + (lane & 3) * 2;
            float ba = sb1[col], bb = sb1[col + 1];
            float f0 = lrelu(c[mt][nt][0] + ba), f1 = lrelu(c[mt][nt][1] + bb);
            float f2 = lrelu(c[mt][nt][2] + ba), f3 = lrelu(c[mt][nt][3] + bb);
            __half h0 = __float2half_rn(f0), h1 = __float2half_rn(f1);
            __half h2 = __float2half_rn(f2), h3 = __float2half_rn(f3);
            *(uint32_t*)(smx + N_XH + r0 * 272 + col * 2)       = packh2(h0, h1);
            *(uint32_t*)(smx + N_XH + (r0 + 8) * 272 + col * 2) = packh2(h2, h3);
            *(uint32_t*)(smx + N_XL + r0 * 272 + col * 2) =
                packh2(__float2half_rn(f0 - __half2float(h0)), __float2half_rn(f1 - __half2float(h1)));
            *(uint32_t*)(smx + N_XL + (r0 + 8) * 272 + col * 2) =
                packh2(__float2half_rn(f2 - __half2float(h2)), __float2half_rn(f3 - __half2float(h3)));
        }
    {
        const uint4* s = (const uint4*)((const char*)g_wimg + BW_W2U);
        uint4* d = (uint4*)(smx + N_WH);
        for (int i = tid; i < 4352; i += 512) d[i] = s[i];
    }
    __syncthreads();

    // GEMM2: K=128, 3-term
    #pragma unroll
    for (int i = 0; i < 2; ++i)
        #pragma unroll
        for (int j = 0; j < 4; ++j)
            #pragma unroll
            for (int r = 0; r < 4; ++r) c[i][j][r] = 0.f;
    #pragma unroll
    for (int k = 0; k < 8; ++k)
        gemm_step3<272, 272>(c, sb + N_XH, sb + N_XL, sb + N_WH, sb + N_W2L,
                             k * 32, k * 32, wm, wn, lane);

    // epilogue2: bias + v4 stores
    {
        const int q = lane & 3;
        const int Lb = wn * 32 + q * 8;
        float c0 = sb2[Lb],     c1 = sb2[Lb + 1], c2 = sb2[Lb + 2], c3 = sb2[Lb + 3];
        float c4 = sb2[Lb + 4], c5 = sb2[Lb + 5], c6 = sb2[Lb + 6], c7 = sb2[Lb + 7];
        #pragma unroll
        for (int mt = 0; mt < 2; ++mt) {
            int r = wm * 32 + mt * 16 + (lane >> 2);
            int nA = n0 + r, nB = n0 + r + 8;
            if (nA < N) {
                float4* p = (float4*)(out + (size_t)nA * 128 + Lb);
                p[0] = make_float4(c[mt][0][0] + c0, c[mt][0][1] + c1, c[mt][1][0] + c2, c[mt][1][1] + c3);
                p[1] = make_float4(c[mt][2][0] + c4, c[mt][2][1] + c5, c[mt][3][0] + c6, c[mt][3][1] + c7);
            }
            if (nB < N) {
                float4* p = (float4*)(out + (size_t)nB * 128 + Lb);
                p[0] = make_float4(c[mt][0][2] + c0, c[mt][0][3] + c1, c[mt][1][2] + c2, c[mt][1][3] + c3);
                p[1] = make_float4(c[mt][2][2] + c4, c[mt][2][3] + c5, c[mt][3][2] + c6, c[mt][3][3] + c7);
            }
        }
    }
}

// ---------------------------------------------------------------------------

extern "C" void kernel_launch(void* const* d_in, const int* in_sizes, int n_in,
                              void* d_out, int out_size)
{
    const float* node_feats = (const float*)d_in[0];
    const float* edge_feats = (const float*)d_in[1];
    const float* msg_w1     = (const float*)d_in[2];
    const float* msg_b1     = (const float*)d_in[3];
    const float* msg_w2     = (const float*)d_in[4];
    const float* msg_b2     = (const float*)d_in[5];
    const float* upd_w1     = (const float*)d_in[6];
    const float* upd_b1     = (const float*)d_in[7];
    const float* upd_w2     = (const float*)d_in[8];
    const float* upd_b2     = (const float*)d_in[9];
    const void*  edge_index = d_in[10];

    const int N = in_sizes[0] / 128;   // 50000
    const int E = in_sizes[1] / 64;    // 800000
    const int nTiles = (E + 127) / 128;

    cudaFuncSetAttribute(edge_mma_kernel, cudaFuncAttributeMaxDynamicSharedMemorySize, E_DYN);
    cudaFuncSetAttribute(node_mma_kernel, cudaFuncAttributeMaxDynamicSharedMemorySize, N_DYN);

    build_wimg_kernel<<<352, 256>>>(msg_w1, msg_w2, upd_w1, upd_w2);
    split_nf_kernel<<<1024, 256>>>(node_feats, N * 64);
    convert_idx_kernel<<<400, 256>>>(edge_index, E);
    zero_agg_kernel<<<400, 256>>>(N * 32);

    edge_mma_kernel<<<148, 512, E_DYN>>>(edge_feats, msg_b1, msg_b2, E, nTiles);

    node_mma_kernel<<<(N + 127) / 128, 512, N_DYN>>>(upd_b1, upd_b2, (float*)d_out, N);
}

// round 8
// speedup vs baseline: 7.3761x; 1.4757x over previous
#include <cuda_runtime.h>
#include <cuda_fp16.h>
#include <cstdint>

// ===========================================================================
// GraphConvLayer via warp-level mma.sync (m16n8k16 fp16, fp32 accum).
// v3: edge kernel = persistent blocks, pure-fp16 weights (1-term GEMMs),
//     double-buffered cp.async X gather. Node kernel = 3-term split (exact-ish).
// ===========================================================================

#define MAX_N 50000
#define MAX_E 800000

__device__ float  g_agg[(size_t)MAX_N * 128];
__device__ int    g_src[MAX_E];
__device__ int    g_dst[MAX_E];
__device__ __half g_nfh[(size_t)MAX_N * 128];
__device__ __half g_nfl[(size_t)MAX_N * 128];
__device__ __half g_efh[(size_t)MAX_E * 64];
// weight images (halves): W1M(25600 hi + 25600 lo) W2M(17408x2) W1U(33792x2) W2U(17408x2)
__device__ __half g_wimg[188416];

// byte offsets into g_wimg
#define BW_W1M 0
#define BW_W2M 102400
#define BW_W1U 172032
#define BW_W2U 307200

// ---------------- helpers ----------------
__device__ __forceinline__ uint32_t smem_u32(const void* p) {
    uint32_t a;
    asm("{ .reg .u64 t; cvta.to.shared.u64 t, %1; cvt.u32.u64 %0, t; }" : "=r"(a) : "l"(p));
    return a;
}
__device__ __forceinline__ float lrelu(float v) { return v >= 0.f ? v : 0.2f * v; }
__device__ __forceinline__ uint32_t packh2(__half a, __half b) {
    __half2 h = __halves2half2(a, b);
    return *reinterpret_cast<uint32_t*>(&h);
}
__device__ __forceinline__ void ldsm4(uint32_t* r, uint32_t a) {
    asm volatile("ldmatrix.sync.aligned.m8n8.x4.shared.b16 {%0,%1,%2,%3}, [%4];"
        : "=r"(r[0]), "=r"(r[1]), "=r"(r[2]), "=r"(r[3]) : "r"(a));
}
__device__ __forceinline__ void mma16816(float* c, const uint32_t* a, uint32_t b0, uint32_t b1) {
    asm volatile("mma.sync.aligned.m16n8k16.row.col.f32.f16.f16.f32 "
        "{%0,%1,%2,%3}, {%4,%5,%6,%7}, {%8,%9}, {%0,%1,%2,%3};"
        : "+f"(c[0]), "+f"(c[1]), "+f"(c[2]), "+f"(c[3])
        : "r"(a[0]), "r"(a[1]), "r"(a[2]), "r"(a[3]), "r"(b0), "r"(b1));
}
__device__ __forceinline__ void red_add_v4(float* p, float a, float b, float c, float d) {
    asm volatile("red.global.add.v4.f32 [%0], {%1, %2, %3, %4};"
        :: "l"(p), "f"(a), "f"(b), "f"(c), "f"(d) : "memory");
}
__device__ __forceinline__ void cp16(uint32_t d, const void* s) {
    asm volatile("cp.async.cg.shared.global [%0], [%1], 16;" :: "r"(d), "l"(s));
}
#define CP_COMMIT() asm volatile("cp.async.commit_group;" ::: "memory")
#define CP_WAIT0()  asm volatile("cp.async.wait_group 0;"  ::: "memory")

// 1-term k16 step: c += Ah*Bh. A row-major rows=m, B = N x K row-major.
template<int AS, int BS>
__device__ __forceinline__ void gemm_step1(float (&c)[2][4][4],
    uint32_t aHi, uint32_t bHi, int akb, int bkb, int wm, int wn, int lane)
{
    const int rs = lane & 15;
    const int hs = (lane >> 4) << 4;
    uint32_t ah[2][4], bh[2][4];
    #pragma unroll
    for (int mt = 0; mt < 2; ++mt)
        ldsm4(ah[mt], aHi + (wm * 32 + mt * 16 + rs) * AS + akb + hs);
    #pragma unroll
    for (int nt = 0; nt < 2; ++nt)
        ldsm4(bh[nt], bHi + (wn * 32 + nt * 16 + rs) * BS + bkb + hs);
    #pragma unroll
    for (int mt = 0; mt < 2; ++mt)
        #pragma unroll
        for (int nt = 0; nt < 2; ++nt) {
            mma16816(c[mt][2 * nt],     ah[mt], bh[nt][0], bh[nt][2]);
            mma16816(c[mt][2 * nt + 1], ah[mt], bh[nt][1], bh[nt][3]);
        }
}

// 3-term k16 step (node kernel): c += Ah*Bh + Ah*Bl + Al*Bh.
template<int AS, int BS>
__device__ __forceinline__ void gemm_step3(float (&c)[2][4][4],
    uint32_t aHi, uint32_t aLo, uint32_t bHi, uint32_t bLo,
    int akb, int bkb, int wm, int wn, int lane)
{
    const int rs = lane & 15;
    const int hs = (lane >> 4) << 4;
    uint32_t ah[2][4], al[2][4], bh[2][4], bl[2][4];
    #pragma unroll
    for (int mt = 0; mt < 2; ++mt) {
        ldsm4(ah[mt], aHi + (wm * 32 + mt * 16 + rs) * AS + akb + hs);
        ldsm4(al[mt], aLo + (wm * 32 + mt * 16 + rs) * AS + akb + hs);
    }
    #pragma unroll
    for (int nt = 0; nt < 2; ++nt) {
        ldsm4(bh[nt], bHi + (wn * 32 + nt * 16 + rs) * BS + bkb + hs);
        ldsm4(bl[nt], bLo + (wn * 32 + nt * 16 + rs) * BS + bkb + hs);
    }
    #pragma unroll
    for (int mt = 0; mt < 2; ++mt)
        #pragma unroll
        for (int nt = 0; nt < 2; ++nt) {
            mma16816(c[mt][2 * nt],     ah[mt], bh[nt][0], bh[nt][2]);
            mma16816(c[mt][2 * nt + 1], ah[mt], bh[nt][1], bh[nt][3]);
            mma16816(c[mt][2 * nt],     ah[mt], bl[nt][0], bl[nt][2]);
            mma16816(c[mt][2 * nt + 1], ah[mt], bl[nt][1], bl[nt][3]);
            mma16816(c[mt][2 * nt],     al[mt], bh[nt][0], bh[nt][2]);
            mma16816(c[mt][2 * nt + 1], al[mt], bh[nt][1], bh[nt][3]);
        }
}

__device__ __forceinline__ void splitpack8(float4 v0, float4 v1, uint4& hi, uint4& lo) {
    float f[8] = {v0.x, v0.y, v0.z, v0.w, v1.x, v1.y, v1.z, v1.w};
    uint32_t hw[4], lw[4];
    #pragma unroll
    for (int j = 0; j < 4; ++j) {
        __half h0 = __float2half_rn(f[2 * j]), h1 = __float2half_rn(f[2 * j + 1]);
        hw[j] = packh2(h0, h1);
        lw[j] = packh2(__float2half_rn(f[2 * j] - __half2float(h0)),
                       __float2half_rn(f[2 * j + 1] - __half2float(h1)));
    }
    hi = make_uint4(hw[0], hw[1], hw[2], hw[3]);
    lo = make_uint4(lw[0], lw[1], lw[2], lw[3]);
}

// ---------------- prologue kernels ----------------
__global__ void build_wimg_kernel(const float* __restrict__ mw1, const float* __restrict__ mw2,
                                  const float* __restrict__ uw1, const float* __restrict__ uw2)
{
    int t = blockIdx.x * blockDim.x + threadIdx.x;
    if (t >= 90112) return;
    const float* src; int K, hoff, lskip; bool perm;
    if (t < 24576)      { src = mw1; K = 192; hoff = 0;      lskip = 25600; perm = false; }
    else if (t < 40960) { t -= 24576; src = mw2; K = 128; hoff = 51200;  lskip = 17408; perm = true; }
    else if (t < 73728) { t -= 40960; src = uw1; K = 256; hoff = 86016;  lskip = 33792; perm = false; }
    else                { t -= 73728; src = uw2; K = 128; hoff = 153600; lskip = 17408; perm = true; }
    int n = t / K, k = t - n * K;
    int stride = K + 8;
    float v = src[(size_t)k * 128 + n];   // W^T[n][k]
    __half h = __float2half_rn(v);
    __half l = __float2half_rn(v - __half2float(h));
    int row = n;
    if (perm) {   // logical col n -> physical row so epilogue gets 8 contiguous logical cols
        int wg = n >> 5, w = n & 31, q = w >> 3, tt = (w >> 1) & 3, r = w & 1;
        row = wg * 32 + tt * 8 + q * 2 + r;
    }
    g_wimg[hoff + row * stride + k]         = h;
    g_wimg[hoff + lskip + row * stride + k] = l;
}

__global__ void split_nf_kernel(const float* __restrict__ src, int n2)
{
    int stride = gridDim.x * blockDim.x;
    for (int i = blockIdx.x * blockDim.x + threadIdx.x; i < n2; i += stride) {
        float2 v = ((const float2*)src)[i];
        __half h0 = __float2half_rn(v.x), h1 = __float2half_rn(v.y);
        ((uint32_t*)g_nfh)[i] = packh2(h0, h1);
        ((uint32_t*)g_nfl)[i] = packh2(__float2half_rn(v.x - __half2float(h0)),
                                       __float2half_rn(v.y - __half2float(h1)));
    }
}

__global__ void tohalf_kernel(const float* __restrict__ src, int n2)
{
    int stride = gridDim.x * blockDim.x;
    for (int i = blockIdx.x * blockDim.x + threadIdx.x; i < n2; i += stride) {
        float2 v = ((const float2*)src)[i];
        ((uint32_t*)g_efh)[i] = packh2(__float2half_rn(v.x), __float2half_rn(v.y));
    }
}

__global__ void convert_idx_kernel(const void* __restrict__ ei, int E)
{
    const int* p32 = (const int*)ei;
    int s = 0;
    #pragma unroll
    for (int i = 0; i < 16; ++i) s |= p32[2 * i + 1];
    const bool is64 = (s == 0);
    const int stride = gridDim.x * blockDim.x;
    if (is64) {
        const long long* p = (const long long*)ei;
        for (int i = blockIdx.x * blockDim.x + threadIdx.x; i < E; i += stride) {
            g_src[i] = (int)p[i];
            g_dst[i] = (int)p[(size_t)E + i];
        }
    } else {
        for (int i = blockIdx.x * blockDim.x + threadIdx.x; i < E; i += stride) {
            g_src[i] = p32[i];
            g_dst[i] = p32[(size_t)E + i];
        }
    }
}

__global__ void zero_agg_kernel(int n4) {
    float4 z = make_float4(0.f, 0.f, 0.f, 0.f);
    float4* p = (float4*)g_agg;
    for (int i = blockIdx.x * blockDim.x + threadIdx.x; i < n4; i += gridDim.x * blockDim.x)
        p[i] = z;
}

// ---------------- edge kernel smem layout (bytes) ----------------
#define E_W1  0        // W1 hi 51200
#define E_W2  51200    // W2 hi 34816
#define E_H   86016    // H hi 128x272 = 34816
#define E_X0  120832   // X hi buf0 128x400 = 51200
#define E_X1  172032   // X hi buf1
#define E_SRC 223232   // 2 x 512
#define E_SB1 224256
#define E_SB2 224768
#define E_DYN 225280

// issue cp.async gather of one tile's X (hi only) into buffer buf
__device__ __forceinline__ void issue_gather(char* smx, int buf, int tile, int E, int tid) {
    const uint32_t xb = smem_u32(smx) + (buf ? E_X1 : E_X0);
    const int e0 = tile * 128;
    #pragma unroll
    for (int j = 0; j < 6; ++j) {
        int t = tid + j * 512;            // 0..3071
        int row = t / 24, ch = t - row * 24;
        int e = e0 + row; if (e >= E) e = E - 1;
        if (ch < 16) {
            int dn = g_dst[e];
            cp16(xb + row * 400 + ch * 16, g_nfh + (size_t)dn * 128 + ch * 8);
        } else {
            cp16(xb + row * 400 + 256 + (ch - 16) * 16, g_efh + (size_t)e * 64 + (ch - 16) * 8);
        }
    }
}

__global__ __launch_bounds__(512, 1)
void edge_mma_kernel(const float* __restrict__ b1g, const float* __restrict__ b2g,
                     int E, int nTiles)
{
    extern __shared__ char smx[];
    const uint32_t sb = smem_u32(smx);
    int*   s_src = (int*)(smx + E_SRC);       // [2][128]
    float* sb1   = (float*)(smx + E_SB1);
    float* sb2   = (float*)(smx + E_SB2);
    const int tid = threadIdx.x, lane = tid & 31, wid = tid >> 5;
    const int wm = wid & 3, wn = wid >> 2;

    if (tid < 128)      sb1[tid] = b1g[tid];
    else if (tid < 256) sb2[tid - 128] = b2g[tid - 128];
    {   // stage W1 hi (51200 B) + W2 hi (34816 B) ONCE
        const uint4* s1 = (const uint4*)((const char*)g_wimg + BW_W1M);
        uint4* d1 = (uint4*)(smx + E_W1);
        for (int i = tid; i < 3200; i += 512) d1[i] = s1[i];
        const uint4* s2 = (const uint4*)((const char*)g_wimg + BW_W2M);
        uint4* d2 = (uint4*)(smx + E_W2);
        for (int i = tid; i < 2176; i += 512) d2[i] = s2[i];
    }

    int tile = blockIdx.x;
    if (tile < nTiles) {
        issue_gather(smx, 0, tile, E, tid);
        if (tid < 128) {
            int e = tile * 128 + tid;
            s_src[tid] = (e < E) ? g_src[e] : -1;
        }
    }
    CP_COMMIT();

    int b = 0;
    for (; tile < nTiles; tile += gridDim.x, b ^= 1) {
        CP_WAIT0();
        __syncthreads();     // X[b], s_src[b] ready; H + X[b^1] free; prev tile fully done

        int nextTile = tile + gridDim.x;
        if (nextTile < nTiles) {
            issue_gather(smx, b ^ 1, nextTile, E, tid);
            if (tid < 128) {
                int e = nextTile * 128 + tid;
                s_src[(b ^ 1) * 128 + tid] = (e < E) ? g_src[e] : -1;
            }
        }
        CP_COMMIT();

        const uint32_t xb = sb + (b ? E_X1 : E_X0);

        // GEMM1: K=192, 1-term
        float c[2][4][4];
        #pragma unroll
        for (int i = 0; i < 2; ++i)
            #pragma unroll
            for (int j = 0; j < 4; ++j)
                #pragma unroll
                for (int r = 0; r < 4; ++r) c[i][j][r] = 0.f;
        #pragma unroll
        for (int k = 0; k < 12; ++k)
            gemm_step1<400, 400>(c, xb, sb + E_W1, k * 32, k * 32, wm, wn, lane);

        // epilogue1: bias+lrelu -> H hi (separate region, no overlay)
        #pragma unroll
        for (int mt = 0; mt < 2; ++mt)
            #pragma unroll
            for (int nt = 0; nt < 4; ++nt) {
                int r0  = wm * 32 + mt * 16 + (lane >> 2);
                int col = wn * 32 + nt * 8 + (lane & 3) * 2;
                float ba = sb1[col], bb = sb1[col + 1];
                float f0 = lrelu(c[mt][nt][0] + ba), f1 = lrelu(c[mt][nt][1] + bb);
                float f2 = lrelu(c[mt][nt][2] + ba), f3 = lrelu(c[mt][nt][3] + bb);
                *(uint32_t*)(smx + E_H + r0 * 272 + col * 2) =
                    packh2(__float2half_rn(f0), __float2half_rn(f1));
                *(uint32_t*)(smx + E_H + (r0 + 8) * 272 + col * 2) =
                    packh2(__float2half_rn(f2), __float2half_rn(f3));
            }
        __syncthreads();     // H complete before GEMM2

        // GEMM2: K=128, 1-term
        #pragma unroll
        for (int i = 0; i < 2; ++i)
            #pragma unroll
            for (int j = 0; j < 4; ++j)
                #pragma unroll
                for (int r = 0; r < 4; ++r) c[i][j][r] = 0.f;
        #pragma unroll
        for (int k = 0; k < 8; ++k)
            gemm_step1<272, 272>(c, sb + E_H, sb + E_W2, k * 32, k * 32, wm, wn, lane);

        // epilogue2: bias + vector scatter-add (W2 col-perm -> 8 contiguous cols)
        {
            const int q = lane & 3;
            const int Lb = wn * 32 + q * 8;
            const int* sp = s_src + b * 128;
            float c0 = sb2[Lb],     c1 = sb2[Lb + 1], c2 = sb2[Lb + 2], c3 = sb2[Lb + 3];
            float c4 = sb2[Lb + 4], c5 = sb2[Lb + 5], c6 = sb2[Lb + 6], c7 = sb2[Lb + 7];
            #pragma unroll
            for (int mt = 0; mt < 2; ++mt) {
                int r = wm * 32 + mt * 16 + (lane >> 2);
                int s0 = sp[r], s1 = sp[r + 8];
                if (s0 >= 0) {
                    float* p = g_agg + (size_t)s0 * 128 + Lb;
                    red_add_v4(p,     c[mt][0][0] + c0, c[mt][0][1] + c1, c[mt][1][0] + c2, c[mt][1][1] + c3);
                    red_add_v4(p + 4, c[mt][2][0] + c4, c[mt][2][1] + c5, c[mt][3][0] + c6, c[mt][3][1] + c7);
                }
                if (s1 >= 0) {
                    float* p = g_agg + (size_t)s1 * 128 + Lb;
                    red_add_v4(p,     c[mt][0][2] + c0, c[mt][0][3] + c1, c[mt][1][2] + c2, c[mt][1][3] + c3);
                    red_add_v4(p + 4, c[mt][2][2] + c4, c[mt][2][3] + c5, c[mt][3][2] + c6, c[mt][3][3] + c7);
                }
            }
        }
    }
}

// ---------------- node kernel smem layout (bytes) ----------------
#define N_WH  0        // W1U hi 67584 | later W2U hi 34816
#define N_W1L 67584
#define N_W2L 34816
#define N_XH  135168   // X chunk hi 34816 (later H hi)
#define N_XL  169984
#define N_SB1 204800
#define N_SB2 205312
#define N_DYN 206848

__global__ __launch_bounds__(512, 1)
void node_mma_kernel(const float* __restrict__ b1g, const float* __restrict__ b2g,
                     float* __restrict__ out, int N)
{
    extern __shared__ char smx[];
    const uint32_t sb = smem_u32(smx);
    float* sb1 = (float*)(smx + N_SB1);
    float* sb2 = (float*)(smx + N_SB2);
    const int tid = threadIdx.x, lane = tid & 31, wid = tid >> 5;
    const int wm = wid & 3, wn = wid >> 2;
    const int n0 = blockIdx.x * 128;

    if (tid < 128)      sb1[tid] = b1g[tid];
    else if (tid < 256) sb2[tid - 128] = b2g[tid - 128];
    {   // stage W1U^T hi+lo (135168 B)
        const uint4* s = (const uint4*)((const char*)g_wimg + BW_W1U);
        uint4* d = (uint4*)(smx + N_WH);
        for (int i = tid; i < 8448; i += 512) d[i] = s[i];
    }
    // X chunk0: node_feats hi/lo from precomputed images
    for (int t = tid; t < 128 * 32; t += 512) {
        int row = t >> 5, ch = t & 31;
        int n = n0 + row; if (n >= N) n = N - 1;
        if (ch < 16)
            *(uint4*)(smx + N_XH + row * 272 + ch * 16) = ((const uint4*)(g_nfh + (size_t)n * 128))[ch];
        else
            *(uint4*)(smx + N_XL + row * 272 + (ch - 16) * 16) = ((const uint4*)(g_nfl + (size_t)n * 128))[ch - 16];
    }
    __syncthreads();

    float c[2][4][4];
    #pragma unroll
    for (int i = 0; i < 2; ++i)
        #pragma unroll
        for (int j = 0; j < 4; ++j)
            #pragma unroll
            for (int r = 0; r < 4; ++r) c[i][j][r] = 0.f;
    #pragma unroll
    for (int k = 0; k < 8; ++k)
        gemm_step3<272, 528>(c, sb + N_XH, sb + N_XL, sb + N_WH, sb + N_W1L,
                             k * 32, k * 32, wm, wn, lane);
    __syncthreads();

    // X chunk1: g_agg fp32 -> hi/lo split fused here
    for (int t = tid; t < 128 * 16; t += 512) {
        int row = t >> 4, ch = t & 15;
        int n = n0 + row; if (n >= N) n = N - 1;
        const float4* bp = (const float4*)(g_agg + (size_t)n * 128 + ch * 8);
        uint4 hi, lo;
        splitpack8(bp[0], bp[1], hi, lo);
        *(uint4*)(smx + N_XH + row * 272 + ch * 16) = hi;
        *(uint4*)(smx + N_XL + row * 272 + ch * 16) = lo;
    }
    __syncthreads();
    #pragma unroll
    for (int k = 0; k < 8; ++k)
        gemm_step3<272, 528>(c, sb + N_XH, sb + N_XL, sb + N_WH, sb + N_W1L,
                             k * 32, 256 + k * 32, wm, wn, lane);
    __syncthreads();

    // epilogue1 + stage W2U
    #pragma unroll
    for (int mt = 0; mt < 2; ++mt)
        #pragma unroll
        for (int nt = 0; nt < 4; ++nt) {
            int r0  = wm * 32 + mt * 16 + (lane >> 2);
            int col = wn * 32 + nt * 8 + (lane & 3) * 2;
            float ba = sb1[col], bb = sb1[col + 1];
            float f0 = lrelu(c[mt][nt][0] + ba), f1 = lrelu(c[mt][nt][1] + bb);
            float f2 = lrelu(c[mt][nt][2] + ba), f3 = lrelu(c[mt][nt][3] + bb);
            __half h0 = __float2half_rn(f0), h1 = __float2half_rn(f1);
            __half h2 = __float2half_rn(f2), h3 = __float2half_rn(f3);
            *(uint32_t*)(smx + N_XH + r0 * 272 + col * 2)       = packh2(h0, h1);
            *(uint32_t*)(smx + N_XH + (r0 + 8) * 272 + col * 2) = packh2(h2, h3);
            *(uint32_t*)(smx + N_XL + r0 * 272 + col * 2) =
                packh2(__float2half_rn(f0 - __half2float(h0)), __float2half_rn(f1 - __half2float(h1)));
            *(uint32_t*)(smx + N_XL + (r0 + 8) * 272 + col * 2) =
                packh2(__float2half_rn(f2 - __half2float(h2)), __float2half_rn(f3 - __half2float(h3)));
        }
    {
        const uint4* s = (const uint4*)((const char*)g_wimg + BW_W2U);
        uint4* d = (uint4*)(smx + N_WH);
        for (int i = tid; i < 4352; i += 512) d[i] = s[i];
    }
    __syncthreads();

    // GEMM2: K=128, 3-term
    #pragma unroll
    for (int i = 0; i < 2; ++i)
        #pragma unroll
        for (int j = 0; j < 4; ++j)
            #pragma unroll
            for (int r = 0; r < 4; ++r) c[i][j][r] = 0.f;
    #pragma unroll
    for (int k = 0; k < 8; ++k)
        gemm_step3<272, 272>(c, sb + N_XH, sb + N_XL, sb + N_WH, sb + N_W2L,
                             k * 32, k * 32, wm, wn, lane);

    // epilogue2: bias + v4 stores
    {
        const int q = lane & 3;
        const int Lb = wn * 32 + q * 8;
        float c0 = sb2[Lb],     c1 = sb2[Lb + 1], c2 = sb2[Lb + 2], c3 = sb2[Lb + 3];
        float c4 = sb2[Lb + 4], c5 = sb2[Lb + 5], c6 = sb2[Lb + 6], c7 = sb2[Lb + 7];
        #pragma unroll
        for (int mt = 0; mt < 2; ++mt) {
            int r = wm * 32 + mt * 16 + (lane >> 2);
            int nA = n0 + r, nB = n0 + r + 8;
            if (nA < N) {
                float4* p = (float4*)(out + (size_t)nA * 128 + Lb);
                p[0] = make_float4(c[mt][0][0] + c0, c[mt][0][1] + c1, c[mt][1][0] + c2, c[mt][1][1] + c3);
                p[1] = make_float4(c[mt][2][0] + c4, c[mt][2][1] + c5, c[mt][3][0] + c6, c[mt][3][1] + c7);
            }
            if (nB < N) {
                float4* p = (float4*)(out + (size_t)nB * 128 + Lb);
                p[0] = make_float4(c[mt][0][2] + c0, c[mt][0][3] + c1, c[mt][1][2] + c2, c[mt][1][3] + c3);
                p[1] = make_float4(c[mt][2][2] + c4, c[mt][2][3] + c5, c[mt][3][2] + c6, c[mt][3][3] + c7);
            }
        }
    }
}

// ---------------------------------------------------------------------------

extern "C" void kernel_launch(void* const* d_in, const int* in_sizes, int n_in,
                              void* d_out, int out_size)
{
    const float* node_feats = (const float*)d_in[0];
    const float* edge_feats = (const float*)d_in[1];
    const float* msg_w1     = (const float*)d_in[2];
    const float* msg_b1     = (const float*)d_in[3];
    const float* msg_w2     = (const float*)d_in[4];
    const float* msg_b2     = (const float*)d_in[5];
    const float* upd_w1     = (const float*)d_in[6];
    const float* upd_b1     = (const float*)d_in[7];
    const float* upd_w2     = (const float*)d_in[8];
    const float* upd_b2     = (const float*)d_in[9];
    const void*  edge_index = d_in[10];

    const int N = in_sizes[0] / 128;   // 50000
    const int E = in_sizes[1] / 64;    // 800000
    const int nTiles = (E + 127) / 128;

    cudaFuncSetAttribute(edge_mma_kernel, cudaFuncAttributeMaxDynamicSharedMemorySize, E_DYN);
    cudaFuncSetAttribute(node_mma_kernel, cudaFuncAttributeMaxDynamicSharedMemorySize, N_DYN);

    build_wimg_kernel<<<352, 256>>>(msg_w1, msg_w2, upd_w1, upd_w2);
    split_nf_kernel<<<1024, 256>>>(node_feats, N * 64);
    tohalf_kernel<<<2048, 256>>>(edge_feats, E * 32);
    convert_idx_kernel<<<400, 256>>>(edge_index, E);
    zero_agg_kernel<<<400, 256>>>(N * 32);

    edge_mma_kernel<<<148, 512, E_DYN>>>(msg_b1, msg_b2, E, nTiles);

    node_mma_kernel<<<(N + 127) / 128, 512, N_DYN>>>(upd_b1, upd_b2, (float*)d_out, N);
}

// round 9
// speedup vs baseline: 7.9425x; 1.0768x over previous
#include <cuda_runtime.h>
#include <cuda_fp16.h>
#include <cstdint>

// ===========================================================================
// GraphConvLayer via warp-level mma.sync (m16n8k16 fp16, fp32 accum).
// v4: single merged prologue kernel; persistent edge kernel (1-term GEMMs,
//     cp.async double-buffered gather); persistent node kernel (GEMM1 2-term
//     A-exact, GEMM2 3-term).
// ===========================================================================

#define MAX_N 50000
#define MAX_E 800000

__device__ float  g_agg[(size_t)MAX_N * 128];
__device__ int    g_src[MAX_E];
__device__ int    g_dst[MAX_E];
__device__ __half g_nfh[(size_t)MAX_N * 128];
__device__ __half g_nfl[(size_t)MAX_N * 128];
__device__ __half g_efh[(size_t)MAX_E * 64];
// weight images (halves): W1M(25600 hi + 25600 lo) W2M(17408x2) W1U(33792x2) W2U(17408x2)
__device__ __half g_wimg[188416];

// byte offsets into g_wimg
#define BW_W1M 0
#define BW_W2M 102400
#define BW_W1U 172032
#define BW_W2U 307200

// ---------------- helpers ----------------
__device__ __forceinline__ uint32_t smem_u32(const void* p) {
    uint32_t a;
    asm("{ .reg .u64 t; cvta.to.shared.u64 t, %1; cvt.u32.u64 %0, t; }" : "=r"(a) : "l"(p));
    return a;
}
__device__ __forceinline__ float lrelu(float v) { return v >= 0.f ? v : 0.2f * v; }
__device__ __forceinline__ uint32_t packh2(__half a, __half b) {
    __half2 h = __halves2half2(a, b);
    return *reinterpret_cast<uint32_t*>(&h);
}
__device__ __forceinline__ void ldsm4(uint32_t* r, uint32_t a) {
    asm volatile("ldmatrix.sync.aligned.m8n8.x4.shared.b16 {%0,%1,%2,%3}, [%4];"
        : "=r"(r[0]), "=r"(r[1]), "=r"(r[2]), "=r"(r[3]) : "r"(a));
}
__device__ __forceinline__ void mma16816(float* c, const uint32_t* a, uint32_t b0, uint32_t b1) {
    asm volatile("mma.sync.aligned.m16n8k16.row.col.f32.f16.f16.f32 "
        "{%0,%1,%2,%3}, {%4,%5,%6,%7}, {%8,%9}, {%0,%1,%2,%3};"
        : "+f"(c[0]), "+f"(c[1]), "+f"(c[2]), "+f"(c[3])
        : "r"(a[0]), "r"(a[1]), "r"(a[2]), "r"(a[3]), "r"(b0), "r"(b1));
}
__device__ __forceinline__ void red_add_v4(float* p, float a, float b, float c, float d) {
    asm volatile("red.global.add.v4.f32 [%0], {%1, %2, %3, %4};"
        :: "l"(p), "f"(a), "f"(b), "f"(c), "f"(d) : "memory");
}
__device__ __forceinline__ void cp16(uint32_t d, const void* s) {
    asm volatile("cp.async.cg.shared.global [%0], [%1], 16;" :: "r"(d), "l"(s));
}
#define CP_COMMIT() asm volatile("cp.async.commit_group;" ::: "memory")
#define CP_WAIT0()  asm volatile("cp.async.wait_group 0;"  ::: "memory")

// 1-term k16 step: c += Ah*Bh.
template<int AS, int BS>
__device__ __forceinline__ void gemm_step1(float (&c)[2][4][4],
    uint32_t aHi, uint32_t bHi, int akb, int bkb, int wm, int wn, int lane)
{
    const int rs = lane & 15;
    const int hs = (lane >> 4) << 4;
    uint32_t ah[2][4], bh[2][4];
    #pragma unroll
    for (int mt = 0; mt < 2; ++mt)
        ldsm4(ah[mt], aHi + (wm * 32 + mt * 16 + rs) * AS + akb + hs);
    #pragma unroll
    for (int nt = 0; nt < 2; ++nt)
        ldsm4(bh[nt], bHi + (wn * 32 + nt * 16 + rs) * BS + bkb + hs);
    #pragma unroll
    for (int mt = 0; mt < 2; ++mt)
        #pragma unroll
        for (int nt = 0; nt < 2; ++nt) {
            mma16816(c[mt][2 * nt],     ah[mt], bh[nt][0], bh[nt][2]);
            mma16816(c[mt][2 * nt + 1], ah[mt], bh[nt][1], bh[nt][3]);
        }
}

// 2-term A-exact: c += Ah*Bh + Al*Bh (weights hi only).
template<int AS, int BS>
__device__ __forceinline__ void gemm_stepA2(float (&c)[2][4][4],
    uint32_t aHi, uint32_t aLo, uint32_t bHi,
    int akb, int bkb, int wm, int wn, int lane)
{
    const int rs = lane & 15;
    const int hs = (lane >> 4) << 4;
    uint32_t ah[2][4], al[2][4], bh[2][4];
    #pragma unroll
    for (int mt = 0; mt < 2; ++mt) {
        ldsm4(ah[mt], aHi + (wm * 32 + mt * 16 + rs) * AS + akb + hs);
        ldsm4(al[mt], aLo + (wm * 32 + mt * 16 + rs) * AS + akb + hs);
    }
    #pragma unroll
    for (int nt = 0; nt < 2; ++nt)
        ldsm4(bh[nt], bHi + (wn * 32 + nt * 16 + rs) * BS + bkb + hs);
    #pragma unroll
    for (int mt = 0; mt < 2; ++mt)
        #pragma unroll
        for (int nt = 0; nt < 2; ++nt) {
            mma16816(c[mt][2 * nt],     ah[mt], bh[nt][0], bh[nt][2]);
            mma16816(c[mt][2 * nt + 1], ah[mt], bh[nt][1], bh[nt][3]);
            mma16816(c[mt][2 * nt],     al[mt], bh[nt][0], bh[nt][2]);
            mma16816(c[mt][2 * nt + 1], al[mt], bh[nt][1], bh[nt][3]);
        }
}

// 3-term: c += Ah*Bh + Ah*Bl + Al*Bh.
template<int AS, int BS>
__device__ __forceinline__ void gemm_step3(float (&c)[2][4][4],
    uint32_t aHi, uint32_t aLo, uint32_t bHi, uint32_t bLo,
    int akb, int bkb, int wm, int wn, int lane)
{
    const int rs = lane & 15;
    const int hs = (lane >> 4) << 4;
    uint32_t ah[2][4], al[2][4], bh[2][4], bl[2][4];
    #pragma unroll
    for (int mt = 0; mt < 2; ++mt) {
        ldsm4(ah[mt], aHi + (wm * 32 + mt * 16 + rs) * AS + akb + hs);
        ldsm4(al[mt], aLo + (wm * 32 + mt * 16 + rs) * AS + akb + hs);
    }
    #pragma unroll
    for (int nt = 0; nt < 2; ++nt) {
        ldsm4(bh[nt], bHi + (wn * 32 + nt * 16 + rs) * BS + bkb + hs);
        ldsm4(bl[nt], bLo + (wn * 32 + nt * 16 + rs) * BS + bkb + hs);
    }
    #pragma unroll
    for (int mt = 0; mt < 2; ++mt)
        #pragma unroll
        for (int nt = 0; nt < 2; ++nt) {
            mma16816(c[mt][2 * nt],     ah[mt], bh[nt][0], bh[nt][2]);
            mma16816(c[mt][2 * nt + 1], ah[mt], bh[nt][1], bh[nt][3]);
            mma16816(c[mt][2 * nt],     ah[mt], bl[nt][0], bl[nt][2]);
            mma16816(c[mt][2 * nt + 1], ah[mt], bl[nt][1], bl[nt][3]);
            mma16816(c[mt][2 * nt],     al[mt], bh[nt][0], bh[nt][2]);
            mma16816(c[mt][2 * nt + 1], al[mt], bh[nt][1], bh[nt][3]);
        }
}

__device__ __forceinline__ void splitpack8(float4 v0, float4 v1, uint4& hi, uint4& lo) {
    float f[8] = {v0.x, v0.y, v0.z, v0.w, v1.x, v1.y, v1.z, v1.w};
    uint32_t hw[4], lw[4];
    #pragma unroll
    for (int j = 0; j < 4; ++j) {
        __half h0 = __float2half_rn(f[2 * j]), h1 = __float2half_rn(f[2 * j + 1]);
        hw[j] = packh2(h0, h1);
        lw[j] = packh2(__float2half_rn(f[2 * j] - __half2float(h0)),
                       __float2half_rn(f[2 * j + 1] - __half2float(h1)));
    }
    hi = make_uint4(hw[0], hw[1], hw[2], hw[3]);
    lo = make_uint4(lw[0], lw[1], lw[2], lw[3]);
}

// ---------------- single merged prologue kernel ----------------
__global__ void prep_kernel(const float* __restrict__ nf, const float* __restrict__ ef,
                            const float* __restrict__ mw1, const float* __restrict__ mw2,
                            const float* __restrict__ uw1, const float* __restrict__ uw2,
                            const void* __restrict__ ei, int N, int E)
{
    const int gs = gridDim.x * blockDim.x;
    const int g0 = blockIdx.x * blockDim.x + threadIdx.x;

    // section 1: weight images
    for (int t = g0; t < 90112; t += gs) {
        int u = t;
        const float* src; int K, hoff, lskip; bool perm;
        if (u < 24576)      { src = mw1; K = 192; hoff = 0;      lskip = 25600; perm = false; }
        else if (u < 40960) { u -= 24576; src = mw2; K = 128; hoff = 51200;  lskip = 17408; perm = true; }
        else if (u < 73728) { u -= 40960; src = uw1; K = 256; hoff = 86016;  lskip = 33792; perm = false; }
        else                { u -= 73728; src = uw2; K = 128; hoff = 153600; lskip = 17408; perm = true; }
        int n = u / K, k = u - n * K;
        int stride = K + 8;
        float v = src[(size_t)k * 128 + n];
        __half h = __float2half_rn(v);
        __half l = __float2half_rn(v - __half2float(h));
        int row = n;
        if (perm) {
            int wg = n >> 5, w = n & 31, q = w >> 3, tt = (w >> 1) & 3, r = w & 1;
            row = wg * 32 + tt * 8 + q * 2 + r;
        }
        g_wimg[hoff + row * stride + k]         = h;
        g_wimg[hoff + lskip + row * stride + k] = l;
    }
    // section 2: node_feats hi/lo images
    for (int i = g0; i < N * 64; i += gs) {
        float2 v = ((const float2*)nf)[i];
        __half h0 = __float2half_rn(v.x), h1 = __float2half_rn(v.y);
        ((uint32_t*)g_nfh)[i] = packh2(h0, h1);
        ((uint32_t*)g_nfl)[i] = packh2(__float2half_rn(v.x - __half2float(h0)),
                                       __float2half_rn(v.y - __half2float(h1)));
    }
    // section 3: edge_feats hi image
    for (int i = g0; i < E * 32; i += gs) {
        float2 v = ((const float2*)ef)[i];
        ((uint32_t*)g_efh)[i] = packh2(__float2half_rn(v.x), __float2half_rn(v.y));
    }
    // section 4: edge_index conversion (int64/int32 auto)
    {
        const int* p32 = (const int*)ei;
        int s = 0;
        #pragma unroll
        for (int i = 0; i < 16; ++i) s |= p32[2 * i + 1];
        if (s == 0) {
            const long long* p = (const long long*)ei;
            for (int i = g0; i < E; i += gs) {
                g_src[i] = (int)p[i];
                g_dst[i] = (int)p[(size_t)E + i];
            }
        } else {
            for (int i = g0; i < E; i += gs) {
                g_src[i] = p32[i];
                g_dst[i] = p32[(size_t)E + i];
            }
        }
    }
    // section 5: zero agg
    {
        float4 z = make_float4(0.f, 0.f, 0.f, 0.f);
        for (int i = g0; i < N * 32; i += gs) ((float4*)g_agg)[i] = z;
    }
}

// ---------------- edge kernel smem layout (bytes) ----------------
#define E_W1  0        // W1 hi 51200
#define E_W2  51200    // W2 hi 34816
#define E_H   86016    // H hi 128x272 = 34816
#define E_X0  120832   // X hi buf0 128x400 = 51200
#define E_X1  172032   // X hi buf1
#define E_SRC 223232   // 2 x 512
#define E_SB1 224256
#define E_SB2 224768
#define E_DYN 225280

__device__ __forceinline__ void issue_gather(char* smx, int buf, int tile, int E, int tid) {
    const uint32_t xb = smem_u32(smx) + (buf ? E_X1 : E_X0);
    const int e0 = tile * 128;
    #pragma unroll
    for (int j = 0; j < 6; ++j) {
        int t = tid + j * 512;
        int row = t / 24, ch = t - row * 24;
        int e = e0 + row; if (e >= E) e = E - 1;
        if (ch < 16) {
            int dn = g_dst[e];
            cp16(xb + row * 400 + ch * 16, g_nfh + (size_t)dn * 128 + ch * 8);
        } else {
            cp16(xb + row * 400 + 256 + (ch - 16) * 16, g_efh + (size_t)e * 64 + (ch - 16) * 8);
        }
    }
}

__global__ __launch_bounds__(512, 1)
void edge_mma_kernel(const float* __restrict__ b1g, const float* __restrict__ b2g,
                     int E, int nTiles)
{
    extern __shared__ char smx[];
    const uint32_t sb = smem_u32(smx);
    int*   s_src = (int*)(smx + E_SRC);
    float* sb1   = (float*)(smx + E_SB1);
    float* sb2   = (float*)(smx + E_SB2);
    const int tid = threadIdx.x, lane = tid & 31, wid = tid >> 5;
    const int wm = wid & 3, wn = wid >> 2;

    if (tid < 128)      sb1[tid] = b1g[tid];
    else if (tid < 256) sb2[tid - 128] = b2g[tid - 128];
    {
        const uint4* s1 = (const uint4*)((const char*)g_wimg + BW_W1M);
        uint4* d1 = (uint4*)(smx + E_W1);
        for (int i = tid; i < 3200; i += 512) d1[i] = s1[i];
        const uint4* s2 = (const uint4*)((const char*)g_wimg + BW_W2M);
        uint4* d2 = (uint4*)(smx + E_W2);
        for (int i = tid; i < 2176; i += 512) d2[i] = s2[i];
    }

    int tile = blockIdx.x;
    if (tile < nTiles) {
        issue_gather(smx, 0, tile, E, tid);
        if (tid < 128) {
            int e = tile * 128 + tid;
            s_src[tid] = (e < E) ? g_src[e] : -1;
        }
    }
    CP_COMMIT();

    int b = 0;
    for (; tile < nTiles; tile += gridDim.x, b ^= 1) {
        CP_WAIT0();
        __syncthreads();

        int nextTile = tile + gridDim.x;
        if (nextTile < nTiles) {
            issue_gather(smx, b ^ 1, nextTile, E, tid);
            if (tid < 128) {
                int e = nextTile * 128 + tid;
                s_src[(b ^ 1) * 128 + tid] = (e < E) ? g_src[e] : -1;
            }
        }
        CP_COMMIT();

        const uint32_t xb = sb + (b ? E_X1 : E_X0);

        float c[2][4][4];
        #pragma unroll
        for (int i = 0; i < 2; ++i)
            #pragma unroll
            for (int j = 0; j < 4; ++j)
                #pragma unroll
                for (int r = 0; r < 4; ++r) c[i][j][r] = 0.f;
        #pragma unroll
        for (int k = 0; k < 12; ++k)
            gemm_step1<400, 400>(c, xb, sb + E_W1, k * 32, k * 32, wm, wn, lane);

        #pragma unroll
        for (int mt = 0; mt < 2; ++mt)
            #pragma unroll
            for (int nt = 0; nt < 4; ++nt) {
                int r0  = wm * 32 + mt * 16 + (lane >> 2);
                int col = wn * 32 + nt * 8 + (lane & 3) * 2;
                float ba = sb1[col], bb = sb1[col + 1];
                float f0 = lrelu(c[mt][nt][0] + ba), f1 = lrelu(c[mt][nt][1] + bb);
                float f2 = lrelu(c[mt][nt][2] + ba), f3 = lrelu(c[mt][nt][3] + bb);
                *(uint32_t*)(smx + E_H + r0 * 272 + col * 2) =
                    packh2(__float2half_rn(f0), __float2half_rn(f1));
                *(uint32_t*)(smx + E_H + (r0 + 8) * 272 + col * 2) =
                    packh2(__float2half_rn(f2), __float2half_rn(f3));
            }
        __syncthreads();

        #pragma unroll
        for (int i = 0; i < 2; ++i)
            #pragma unroll
            for (int j = 0; j < 4; ++j)
                #pragma unroll
                for (int r = 0; r < 4; ++r) c[i][j][r] = 0.f;
        #pragma unroll
        for (int k = 0; k < 8; ++k)
            gemm_step1<272, 272>(c, sb + E_H, sb + E_W2, k * 32, k * 32, wm, wn, lane);

        {
            const int q = lane & 3;
            const int Lb = wn * 32 + q * 8;
            const int* sp = s_src + b * 128;
            float c0 = sb2[Lb],     c1 = sb2[Lb + 1], c2 = sb2[Lb + 2], c3 = sb2[Lb + 3];
            float c4 = sb2[Lb + 4], c5 = sb2[Lb + 5], c6 = sb2[Lb + 6], c7 = sb2[Lb + 7];
            #pragma unroll
            for (int mt = 0; mt < 2; ++mt) {
                int r = wm * 32 + mt * 16 + (lane >> 2);
                int s0 = sp[r], s1 = sp[r + 8];
                if (s0 >= 0) {
                    float* p = g_agg + (size_t)s0 * 128 + Lb;
                    red_add_v4(p,     c[mt][0][0] + c0, c[mt][0][1] + c1, c[mt][1][0] + c2, c[mt][1][1] + c3);
                    red_add_v4(p + 4, c[mt][2][0] + c4, c[mt][2][1] + c5, c[mt][3][0] + c6, c[mt][3][1] + c7);
                }
                if (s1 >= 0) {
                    float* p = g_agg + (size_t)s1 * 128 + Lb;
                    red_add_v4(p,     c[mt][0][2] + c0, c[mt][0][3] + c1, c[mt][1][2] + c2, c[mt][1][3] + c3);
                    red_add_v4(p + 4, c[mt][2][2] + c4, c[mt][2][3] + c5, c[mt][3][2] + c6, c[mt][3][3] + c7);
                }
            }
        }
    }
}

// ---------------- persistent node kernel smem layout (bytes) ----------------
#define P_W1  0        // W1U hi, stride 528, 67584
#define P_W2H 67584    // W2U hi, stride 272, 34816
#define P_W2L 102400   // W2U lo, 34816
#define P_XH  137216   // X hi / H hi, stride 272, 34816
#define P_XL  172032   // X lo / H lo, 34816
#define P_SB1 206848
#define P_SB2 207360
#define P_DYN 207872

__global__ __launch_bounds__(512, 1)
void node_mma_kernel(const float* __restrict__ b1g, const float* __restrict__ b2g,
                     float* __restrict__ out, int N, int nTiles)
{
    extern __shared__ char smx[];
    const uint32_t sb = smem_u32(smx);
    float* sb1 = (float*)(smx + P_SB1);
    float* sb2 = (float*)(smx + P_SB2);
    const int tid = threadIdx.x, lane = tid & 31, wid = tid >> 5;
    const int wm = wid & 3, wn = wid >> 2;

    if (tid < 128)      sb1[tid] = b1g[tid];
    else if (tid < 256) sb2[tid - 128] = b2g[tid - 128];
    {   // stage W1U hi (67584 B) + W2U hi+lo (69632 B) ONCE
        const uint4* s1 = (const uint4*)((const char*)g_wimg + BW_W1U);
        uint4* d1 = (uint4*)(smx + P_W1);
        for (int i = tid; i < 4224; i += 512) d1[i] = s1[i];
        const uint4* s2 = (const uint4*)((const char*)g_wimg + BW_W2U);
        uint4* d2 = (uint4*)(smx + P_W2H);
        for (int i = tid; i < 4352; i += 512) d2[i] = s2[i];
    }

    for (int tile = blockIdx.x; tile < nTiles; tile += gridDim.x) {
        const int n0 = tile * 128;
        __syncthreads();        // previous tile done with X/H regions

        // X chunk0: node_feats hi/lo
        for (int t = tid; t < 128 * 32; t += 512) {
            int row = t >> 5, ch = t & 31;
            int n = n0 + row; if (n >= N) n = N - 1;
            if (ch < 16)
                *(uint4*)(smx + P_XH + row * 272 + ch * 16) = ((const uint4*)(g_nfh + (size_t)n * 128))[ch];
            else
                *(uint4*)(smx + P_XL + row * 272 + (ch - 16) * 16) = ((const uint4*)(g_nfl + (size_t)n * 128))[ch - 16];
        }
        __syncthreads();

        float c[2][4][4];
        #pragma unroll
        for (int i = 0; i < 2; ++i)
            #pragma unroll
            for (int j = 0; j < 4; ++j)
                #pragma unroll
                for (int r = 0; r < 4; ++r) c[i][j][r] = 0.f;
        #pragma unroll
        for (int k = 0; k < 8; ++k)
            gemm_stepA2<272, 528>(c, sb + P_XH, sb + P_XL, sb + P_W1,
                                  k * 32, k * 32, wm, wn, lane);
        __syncthreads();        // X consumed before chunk1 overwrite

        // X chunk1: g_agg fp32 -> hi/lo
        for (int t = tid; t < 128 * 16; t += 512) {
            int row = t >> 4, ch = t & 15;
            int n = n0 + row; if (n >= N) n = N - 1;
            const float4* bp = (const float4*)(g_agg + (size_t)n * 128 + ch * 8);
            uint4 hi, lo;
            splitpack8(bp[0], bp[1], hi, lo);
            *(uint4*)(smx + P_XH + row * 272 + ch * 16) = hi;
            *(uint4*)(smx + P_XL + row * 272 + ch * 16) = lo;
        }
        __syncthreads();
        #pragma unroll
        for (int k = 0; k < 8; ++k)
            gemm_stepA2<272, 528>(c, sb + P_XH, sb + P_XL, sb + P_W1,
                                  k * 32, 256 + k * 32, wm, wn, lane);
        __syncthreads();        // GEMM1 reads done before H overlay

        // epilogue1: bias+lrelu -> H hi/lo (overlays X region)
        #pragma unroll
        for (int mt = 0; mt < 2; ++mt)
            #pragma unroll
            for (int nt = 0; nt < 4; ++nt) {
                int r0  = wm * 32 + mt * 16 + (lane >> 2);
                int col = wn * 32 + nt * 8 + (lane & 3) * 2;
                float ba = sb1[col], bb = sb1[col + 1];
                float f0 = lrelu(c[mt][nt][0] + ba), f1 = lrelu(c[mt][nt][1] + bb);
                float f2 = lrelu(c[mt][nt][2] + ba), f3 = lrelu(c[mt][nt][3] + bb);
                __half h0 = __float2half_rn(f0), h1 = __float2half_rn(f1);
                __half h2 = __float2half_rn(f2), h3 = __float2half_rn(f3);
                *(uint32_t*)(smx + P_XH + r0 * 272 + col * 2)       = packh2(h0, h1);
                *(uint32_t*)(smx + P_XH + (r0 + 8) * 272 + col * 2) = packh2(h2, h3);
                *(uint32_t*)(smx + P_XL + r0 * 272 + col * 2) =
                    packh2(__float2half_rn(f0 - __half2float(h0)), __float2half_rn(f1 - __half2float(h1)));
                *(uint32_t*)(smx + P_XL + (r0 + 8) * 272 + col * 2) =
                    packh2(__float2half_rn(f2 - __half2float(h2)), __float2half_rn(f3 - __half2float(h3)));
            }
        __syncthreads();

        // GEMM2: K=128, 3-term (H hi/lo x W2 hi/lo)
        #pragma unroll
        for (int i = 0; i < 2; ++i)
            #pragma unroll
            for (int j = 0; j < 4; ++j)
                #pragma unroll
                for (int r = 0; r < 4; ++r) c[i][j][r] = 0.f;
        #pragma unroll
        for (int k = 0; k < 8; ++k)
            gemm_step3<272, 272>(c, sb + P_XH, sb + P_XL, sb + P_W2H, sb + P_W2L,
                                 k * 32, k * 32, wm, wn, lane);

        // epilogue2: bias + v4 stores
        {
            const int q = lane & 3;
            const int Lb = wn * 32 + q * 8;
            float c0 = sb2[Lb],     c1 = sb2[Lb + 1], c2 = sb2[Lb + 2], c3 = sb2[Lb + 3];
            float c4 = sb2[Lb + 4], c5 = sb2[Lb + 5], c6 = sb2[Lb + 6], c7 = sb2[Lb + 7];
            #pragma unroll
            for (int mt = 0; mt < 2; ++mt) {
                int r = wm * 32 + mt * 16 + (lane >> 2);
                int nA = n0 + r, nB = n0 + r + 8;
                if (nA < N) {
                    float4* p = (float4*)(out + (size_t)nA * 128 + Lb);
                    p[0] = make_float4(c[mt][0][0] + c0, c[mt][0][1] + c1, c[mt][1][0] + c2, c[mt][1][1] + c3);
                    p[1] = make_float4(c[mt][2][0] + c4, c[mt][2][1] + c5, c[mt][3][0] + c6, c[mt][3][1] + c7);
                }
                if (nB < N) {
                    float4* p = (float4*)(out + (size_t)nB * 128 + Lb);
                    p[0] = make_float4(c[mt][0][2] + c0, c[mt][0][3] + c1, c[mt][1][2] + c2, c[mt][1][3] + c3);
                    p[1] = make_float4(c[mt][2][2] + c4, c[mt][2][3] + c5, c[mt][3][2] + c6, c[mt][3][3] + c7);
                }
            }
        }
    }
}

// ---------------------------------------------------------------------------

extern "C" void kernel_launch(void* const* d_in, const int* in_sizes, int n_in,
                              void* d_out, int out_size)
{
    const float* node_feats = (const float*)d_in[0];
    const float* edge_feats = (const float*)d_in[1];
    const float* msg_w1     = (const float*)d_in[2];
    const float* msg_b1     = (const float*)d_in[3];
    const float* msg_w2     = (const float*)d_in[4];
    const float* msg_b2     = (const float*)d_in[5];
    const float* upd_w1     = (const float*)d_in[6];
    const float* upd_b1     = (const float*)d_in[7];
    const float* upd_w2     = (const float*)d_in[8];
    const float* upd_b2     = (const float*)d_in[9];
    const void*  edge_index = d_in[10];

    const int N = in_sizes[0] / 128;   // 50000
    const int E = in_sizes[1] / 64;    // 800000
    const int nTiles  = (E + 127) / 128;
    const int nNTiles = (N + 127) / 128;

    cudaFuncSetAttribute(edge_mma_kernel, cudaFuncAttributeMaxDynamicSharedMemorySize, E_DYN);
    cudaFuncSetAttribute(node_mma_kernel, cudaFuncAttributeMaxDynamicSharedMemorySize, P_DYN);

    prep_kernel<<<2048, 256>>>(node_feats, edge_feats, msg_w1, msg_w2,
                               upd_w1, upd_w2, edge_index, N, E);

    edge_mma_kernel<<<148, 512, E_DYN>>>(msg_b1, msg_b2, E, nTiles);

    node_mma_kernel<<<148, 512, P_DYN>>>(upd_b1, upd_b2, (float*)d_out, N, nNTiles);
}

// round 10
// speedup vs baseline: 8.6038x; 1.0833x over previous
#include <cuda_runtime.h>
#include <cuda_fp16.h>
#include <cstdint>

// ===========================================================================
// GraphConvLayer via warp-level mma.sync (m16n8k16 fp16, fp32 accum).
// v5: prep no longer materializes an fp16 edge_feats image — the edge kernel
//     cp.asyncs raw fp32 edge_feats into a smem staging strip and converts
//     in place (H overlays the consumed X buffer to pay for the staging).
// ===========================================================================

#define MAX_N 50000
#define MAX_E 800000

__device__ float  g_agg[(size_t)MAX_N * 128];
__device__ int    g_src[MAX_E];
__device__ int    g_dst[MAX_E];
__device__ __half g_nfh[(size_t)MAX_N * 128];
__device__ __half g_nfl[(size_t)MAX_N * 128];
// weight images (halves): W1M(25600 hi + 25600 lo) W2M(17408x2) W1U(33792x2) W2U(17408x2)
__device__ __half g_wimg[188416];

// byte offsets into g_wimg
#define BW_W1M 0
#define BW_W2M 102400
#define BW_W1U 172032
#define BW_W2U 307200

// ---------------- helpers ----------------
__device__ __forceinline__ uint32_t smem_u32(const void* p) {
    uint32_t a;
    asm("{ .reg .u64 t; cvta.to.shared.u64 t, %1; cvt.u32.u64 %0, t; }" : "=r"(a) : "l"(p));
    return a;
}
__device__ __forceinline__ float lrelu(float v) { return v >= 0.f ? v : 0.2f * v; }
__device__ __forceinline__ uint32_t packh2(__half a, __half b) {
    __half2 h = __halves2half2(a, b);
    return *reinterpret_cast<uint32_t*>(&h);
}
__device__ __forceinline__ void ldsm4(uint32_t* r, uint32_t a) {
    asm volatile("ldmatrix.sync.aligned.m8n8.x4.shared.b16 {%0,%1,%2,%3}, [%4];"
        : "=r"(r[0]), "=r"(r[1]), "=r"(r[2]), "=r"(r[3]) : "r"(a));
}
__device__ __forceinline__ void mma16816(float* c, const uint32_t* a, uint32_t b0, uint32_t b1) {
    asm volatile("mma.sync.aligned.m16n8k16.row.col.f32.f16.f16.f32 "
        "{%0,%1,%2,%3}, {%4,%5,%6,%7}, {%8,%9}, {%0,%1,%2,%3};"
        : "+f"(c[0]), "+f"(c[1]), "+f"(c[2]), "+f"(c[3])
        : "r"(a[0]), "r"(a[1]), "r"(a[2]), "r"(a[3]), "r"(b0), "r"(b1));
}
__device__ __forceinline__ void red_add_v4(float* p, float a, float b, float c, float d) {
    asm volatile("red.global.add.v4.f32 [%0], {%1, %2, %3, %4};"
        :: "l"(p), "f"(a), "f"(b), "f"(c), "f"(d) : "memory");
}
__device__ __forceinline__ void cp16(uint32_t d, const void* s) {
    asm volatile("cp.async.cg.shared.global [%0], [%1], 16;" :: "r"(d), "l"(s));
}
#define CP_COMMIT() asm volatile("cp.async.commit_group;" ::: "memory")
#define CP_WAIT0()  asm volatile("cp.async.wait_group 0;"  ::: "memory")

// 1-term k16 step: c += Ah*Bh.
template<int AS, int BS>
__device__ __forceinline__ void gemm_step1(float (&c)[2][4][4],
    uint32_t aHi, uint32_t bHi, int akb, int bkb, int wm, int wn, int lane)
{
    const int rs = lane & 15;
    const int hs = (lane >> 4) << 4;
    uint32_t ah[2][4], bh[2][4];
    #pragma unroll
    for (int mt = 0; mt < 2; ++mt)
        ldsm4(ah[mt], aHi + (wm * 32 + mt * 16 + rs) * AS + akb + hs);
    #pragma unroll
    for (int nt = 0; nt < 2; ++nt)
        ldsm4(bh[nt], bHi + (wn * 32 + nt * 16 + rs) * BS + bkb + hs);
    #pragma unroll
    for (int mt = 0; mt < 2; ++mt)
        #pragma unroll
        for (int nt = 0; nt < 2; ++nt) {
            mma16816(c[mt][2 * nt],     ah[mt], bh[nt][0], bh[nt][2]);
            mma16816(c[mt][2 * nt + 1], ah[mt], bh[nt][1], bh[nt][3]);
        }
}

// 2-term A-exact: c += Ah*Bh + Al*Bh (weights hi only).
template<int AS, int BS>
__device__ __forceinline__ void gemm_stepA2(float (&c)[2][4][4],
    uint32_t aHi, uint32_t aLo, uint32_t bHi,
    int akb, int bkb, int wm, int wn, int lane)
{
    const int rs = lane & 15;
    const int hs = (lane >> 4) << 4;
    uint32_t ah[2][4], al[2][4], bh[2][4];
    #pragma unroll
    for (int mt = 0; mt < 2; ++mt) {
        ldsm4(ah[mt], aHi + (wm * 32 + mt * 16 + rs) * AS + akb + hs);
        ldsm4(al[mt], aLo + (wm * 32 + mt * 16 + rs) * AS + akb + hs);
    }
    #pragma unroll
    for (int nt = 0; nt < 2; ++nt)
        ldsm4(bh[nt], bHi + (wn * 32 + nt * 16 + rs) * BS + bkb + hs);
    #pragma unroll
    for (int mt = 0; mt < 2; ++mt)
        #pragma unroll
        for (int nt = 0; nt < 2; ++nt) {
            mma16816(c[mt][2 * nt],     ah[mt], bh[nt][0], bh[nt][2]);
            mma16816(c[mt][2 * nt + 1], ah[mt], bh[nt][1], bh[nt][3]);
            mma16816(c[mt][2 * nt],     al[mt], bh[nt][0], bh[nt][2]);
            mma16816(c[mt][2 * nt + 1], al[mt], bh[nt][1], bh[nt][3]);
        }
}

// 3-term: c += Ah*Bh + Ah*Bl + Al*Bh.
template<int AS, int BS>
__device__ __forceinline__ void gemm_step3(float (&c)[2][4][4],
    uint32_t aHi, uint32_t aLo, uint32_t bHi, uint32_t bLo,
    int akb, int bkb, int wm, int wn, int lane)
{
    const int rs = lane & 15;
    const int hs = (lane >> 4) << 4;
    uint32_t ah[2][4], al[2][4], bh[2][4], bl[2][4];
    #pragma unroll
    for (int mt = 0; mt < 2; ++mt) {
        ldsm4(ah[mt], aHi + (wm * 32 + mt * 16 + rs) * AS + akb + hs);
        ldsm4(al[mt], aLo + (wm * 32 + mt * 16 + rs) * AS + akb + hs);
    }
    #pragma unroll
    for (int nt = 0; nt < 2; ++nt) {
        ldsm4(bh[nt], bHi + (wn * 32 + nt * 16 + rs) * BS + bkb + hs);
        ldsm4(bl[nt], bLo + (wn * 32 + nt * 16 + rs) * BS + bkb + hs);
    }
    #pragma unroll
    for (int mt = 0; mt < 2; ++mt)
        #pragma unroll
        for (int nt = 0; nt < 2; ++nt) {
            mma16816(c[mt][2 * nt],     ah[mt], bh[nt][0], bh[nt][2]);
            mma16816(c[mt][2 * nt + 1], ah[mt], bh[nt][1], bh[nt][3]);
            mma16816(c[mt][2 * nt],     ah[mt], bl[nt][0], bl[nt][2]);
            mma16816(c[mt][2 * nt + 1], ah[mt], bl[nt][1], bl[nt][3]);
            mma16816(c[mt][2 * nt],     al[mt], bh[nt][0], bh[nt][2]);
            mma16816(c[mt][2 * nt + 1], al[mt], bh[nt][1], bh[nt][3]);
        }
}

__device__ __forceinline__ void splitpack8(float4 v0, float4 v1, uint4& hi, uint4& lo) {
    float f[8] = {v0.x, v0.y, v0.z, v0.w, v1.x, v1.y, v1.z, v1.w};
    uint32_t hw[4], lw[4];
    #pragma unroll
    for (int j = 0; j < 4; ++j) {
        __half h0 = __float2half_rn(f[2 * j]), h1 = __float2half_rn(f[2 * j + 1]);
        hw[j] = packh2(h0, h1);
        lw[j] = packh2(__float2half_rn(f[2 * j] - __half2float(h0)),
                       __float2half_rn(f[2 * j + 1] - __half2float(h1)));
    }
    hi = make_uint4(hw[0], hw[1], hw[2], hw[3]);
    lo = make_uint4(lw[0], lw[1], lw[2], lw[3]);
}

// ---------------- single merged prologue kernel ----------------
__global__ void prep_kernel(const float* __restrict__ nf,
                            const float* __restrict__ mw1, const float* __restrict__ mw2,
                            const float* __restrict__ uw1, const float* __restrict__ uw2,
                            const void* __restrict__ ei, int N, int E)
{
    const int gs = gridDim.x * blockDim.x;
    const int g0 = blockIdx.x * blockDim.x + threadIdx.x;

    // section 1: weight images
    for (int t = g0; t < 90112; t += gs) {
        int u = t;
        const float* src; int K, hoff, lskip; bool perm;
        if (u < 24576)      { src = mw1; K = 192; hoff = 0;      lskip = 25600; perm = false; }
        else if (u < 40960) { u -= 24576; src = mw2; K = 128; hoff = 51200;  lskip = 17408; perm = true; }
        else if (u < 73728) { u -= 40960; src = uw1; K = 256; hoff = 86016;  lskip = 33792; perm = false; }
        else                { u -= 73728; src = uw2; K = 128; hoff = 153600; lskip = 17408; perm = true; }
        int n = u / K, k = u - n * K;
        int stride = K + 8;
        float v = src[(size_t)k * 128 + n];
        __half h = __float2half_rn(v);
        __half l = __float2half_rn(v - __half2float(h));
        int row = n;
        if (perm) {
            int wg = n >> 5, w = n & 31, q = w >> 3, tt = (w >> 1) & 3, r = w & 1;
            row = wg * 32 + tt * 8 + q * 2 + r;
        }
        g_wimg[hoff + row * stride + k]         = h;
        g_wimg[hoff + lskip + row * stride + k] = l;
    }
    // section 2: node_feats hi/lo images
    for (int i = g0; i < N * 64; i += gs) {
        float2 v = ((const float2*)nf)[i];
        __half h0 = __float2half_rn(v.x), h1 = __float2half_rn(v.y);
        ((uint32_t*)g_nfh)[i] = packh2(h0, h1);
        ((uint32_t*)g_nfl)[i] = packh2(__float2half_rn(v.x - __half2float(h0)),
                                       __float2half_rn(v.y - __half2float(h1)));
    }
    // section 3: edge_index conversion (int64/int32 auto)
    {
        const int* p32 = (const int*)ei;
        int s = 0;
        #pragma unroll
        for (int i = 0; i < 16; ++i) s |= p32[2 * i + 1];
        if (s == 0) {
            const long long* p = (const long long*)ei;
            for (int i = g0; i < E; i += gs) {
                g_src[i] = (int)p[i];
                g_dst[i] = (int)p[(size_t)E + i];
            }
        } else {
            for (int i = g0; i < E; i += gs) {
                g_src[i] = p32[i];
                g_dst[i] = p32[(size_t)E + i];
            }
        }
    }
    // section 4: zero agg
    {
        float4 z = make_float4(0.f, 0.f, 0.f, 0.f);
        for (int i = g0; i < N * 32; i += gs) ((float4*)g_agg)[i] = z;
    }
}

// ---------------- edge kernel smem layout (bytes) ----------------
#define E_W1  0        // W1 hi 51200 (stride 400)
#define E_W2  51200    // W2 hi 34816 (stride 272)
#define E_X0  86016    // X hi buf0 128x400 = 51200 (H overlays, stride 272)
#define E_X1  137216   // X hi buf1
#define E_EF0 188416   // fp32 edge_feats staging 128x256 = 32768 (single buf)
#define E_SRC 221184   // 2 x 512
#define E_SB1 222208
#define E_SB2 222720
#define E_DYN 223232

// prefetch one tile: node fp16 -> X[buf], raw fp32 edge_feats -> staging
__device__ __forceinline__ void issue_gather(char* smx, int buf, int tile, int E, int tid,
                                             const float* __restrict__ ef) {
    const uint32_t xb = smem_u32(smx) + (buf ? E_X1 : E_X0);
    const uint32_t sf = smem_u32(smx) + E_EF0;
    const int e0 = tile * 128;
    #pragma unroll
    for (int j = 0; j < 8; ++j) {
        int t = tid + j * 512;            // 0..4095
        int row = t >> 5, ch = t & 31;
        int e = e0 + row; if (e >= E) e = E - 1;
        if (ch < 16) {
            int dn = g_dst[e];
            cp16(xb + row * 400 + ch * 16, g_nfh + (size_t)dn * 128 + ch * 8);
        } else {
            cp16(sf + row * 256 + (ch - 16) * 16, ef + (size_t)e * 64 + (ch - 16) * 4);
        }
    }
}

__global__ __launch_bounds__(512, 1)
void edge_mma_kernel(const float* __restrict__ edge_feats,
                     const float* __restrict__ b1g, const float* __restrict__ b2g,
                     int E, int nTiles)
{
    extern __shared__ char smx[];
    const uint32_t sb = smem_u32(smx);
    int*   s_src = (int*)(smx + E_SRC);
    float* sb1   = (float*)(smx + E_SB1);
    float* sb2   = (float*)(smx + E_SB2);
    const int tid = threadIdx.x, lane = tid & 31, wid = tid >> 5;
    const int wm = wid & 3, wn = wid >> 2;

    if (tid < 128)      sb1[tid] = b1g[tid];
    else if (tid < 256) sb2[tid - 128] = b2g[tid - 128];
    {
        const uint4* s1 = (const uint4*)((const char*)g_wimg + BW_W1M);
        uint4* d1 = (uint4*)(smx + E_W1);
        for (int i = tid; i < 3200; i += 512) d1[i] = s1[i];
        const uint4* s2 = (const uint4*)((const char*)g_wimg + BW_W2M);
        uint4* d2 = (uint4*)(smx + E_W2);
        for (int i = tid; i < 2176; i += 512) d2[i] = s2[i];
    }

    int tile = blockIdx.x;
    if (tile < nTiles) {
        issue_gather(smx, 0, tile, E, tid, edge_feats);
        if (tid < 128) {
            int e = tile * 128 + tid;
            s_src[tid] = (e < E) ? g_src[e] : -1;
        }
    }
    CP_COMMIT();

    int b = 0;
    for (; tile < nTiles; tile += gridDim.x, b ^= 1) {
        CP_WAIT0();
        __syncthreads();     // X[b] node + staging + s_src[b] ready; prev tile done

        const uint32_t xb = sb + (b ? E_X1 : E_X0);
        char* xp = smx + (b ? E_X1 : E_X0);

        // convert fp32 staging -> fp16 edge slots of X[b]
        for (int t = tid; t < 1024; t += 512) {
            int row = t >> 3, q = t & 7;
            const float4* sp = (const float4*)(smx + E_EF0 + row * 256 + q * 32);
            float4 v0 = sp[0], v1 = sp[1];
            uint32_t w0 = packh2(__float2half_rn(v0.x), __float2half_rn(v0.y));
            uint32_t w1 = packh2(__float2half_rn(v0.z), __float2half_rn(v0.w));
            uint32_t w2 = packh2(__float2half_rn(v1.x), __float2half_rn(v1.y));
            uint32_t w3 = packh2(__float2half_rn(v1.z), __float2half_rn(v1.w));
            *(uint4*)(xp + row * 400 + 256 + q * 16) = make_uint4(w0, w1, w2, w3);
        }
        __syncthreads();     // staging consumed, X[b] fully built

        int nextTile = tile + gridDim.x;
        if (nextTile < nTiles) {
            issue_gather(smx, b ^ 1, nextTile, E, tid, edge_feats);
            if (tid < 128) {
                int e = nextTile * 128 + tid;
                s_src[(b ^ 1) * 128 + tid] = (e < E) ? g_src[e] : -1;
            }
        }
        CP_COMMIT();

        // GEMM1: K=192, 1-term
        float c[2][4][4];
        #pragma unroll
        for (int i = 0; i < 2; ++i)
            #pragma unroll
            for (int j = 0; j < 4; ++j)
                #pragma unroll
                for (int r = 0; r < 4; ++r) c[i][j][r] = 0.f;
        #pragma unroll
        for (int k = 0; k < 12; ++k)
            gemm_step1<400, 400>(c, xb, sb + E_W1, k * 32, k * 32, wm, wn, lane);
        __syncthreads();     // all X[b] reads done before H overlay

        // epilogue1: bias+lrelu -> H hi (overlays X[b], stride 272)
        #pragma unroll
        for (int mt = 0; mt < 2; ++mt)
            #pragma unroll
            for (int nt = 0; nt < 4; ++nt) {
                int r0  = wm * 32 + mt * 16 + (lane >> 2);
                int col = wn * 32 + nt * 8 + (lane & 3) * 2;
                float ba = sb1[col], bb = sb1[col + 1];
                float f0 = lrelu(c[mt][nt][0] + ba), f1 = lrelu(c[mt][nt][1] + bb);
                float f2 = lrelu(c[mt][nt][2] + ba), f3 = lrelu(c[mt][nt][3] + bb);
                *(uint32_t*)(xp + r0 * 272 + col * 2) =
                    packh2(__float2half_rn(f0), __float2half_rn(f1));
                *(uint32_t*)(xp + (r0 + 8) * 272 + col * 2) =
                    packh2(__float2half_rn(f2), __float2half_rn(f3));
            }
        __syncthreads();     // H complete

        // GEMM2: K=128, 1-term
        #pragma unroll
        for (int i = 0; i < 2; ++i)
            #pragma unroll
            for (int j = 0; j < 4; ++j)
                #pragma unroll
                for (int r = 0; r < 4; ++r) c[i][j][r] = 0.f;
        #pragma unroll
        for (int k = 0; k < 8; ++k)
            gemm_step1<272, 272>(c, xb, sb + E_W2, k * 32, k * 32, wm, wn, lane);

        // epilogue2: bias + vector scatter-add
        {
            const int q = lane & 3;
            const int Lb = wn * 32 + q * 8;
            const int* sp = s_src + b * 128;
            float c0 = sb2[Lb],     c1 = sb2[Lb + 1], c2 = sb2[Lb + 2], c3 = sb2[Lb + 3];
            float c4 = sb2[Lb + 4], c5 = sb2[Lb + 5], c6 = sb2[Lb + 6], c7 = sb2[Lb + 7];
            #pragma unroll
            for (int mt = 0; mt < 2; ++mt) {
                int r = wm * 32 + mt * 16 + (lane >> 2);
                int s0 = sp[r], s1 = sp[r + 8];
                if (s0 >= 0) {
                    float* p = g_agg + (size_t)s0 * 128 + Lb;
                    red_add_v4(p,     c[mt][0][0] + c0, c[mt][0][1] + c1, c[mt][1][0] + c2, c[mt][1][1] + c3);
                    red_add_v4(p + 4, c[mt][2][0] + c4, c[mt][2][1] + c5, c[mt][3][0] + c6, c[mt][3][1] + c7);
                }
                if (s1 >= 0) {
                    float* p = g_agg + (size_t)s1 * 128 + Lb;
                    red_add_v4(p,     c[mt][0][2] + c0, c[mt][0][3] + c1, c[mt][1][2] + c2, c[mt][1][3] + c3);
                    red_add_v4(p + 4, c[mt][2][2] + c4, c[mt][2][3] + c5, c[mt][3][2] + c6, c[mt][3][3] + c7);
                }
            }
        }
    }
}

// ---------------- persistent node kernel smem layout (bytes) ----------------
#define P_W1  0        // W1U hi, stride 528, 67584
#define P_W2H 67584    // W2U hi, stride 272, 34816
#define P_W2L 102400   // W2U lo, 34816
#define P_XH  137216   // X hi / H hi, stride 272, 34816
#define P_XL  172032   // X lo / H lo, 34816
#define P_SB1 206848
#define P_SB2 207360
#define P_DYN 207872

__global__ __launch_bounds__(512, 1)
void node_mma_kernel(const float* __restrict__ b1g, const float* __restrict__ b2g,
                     float* __restrict__ out, int N, int nTiles)
{
    extern __shared__ char smx[];
    const uint32_t sb = smem_u32(smx);
    float* sb1 = (float*)(smx + P_SB1);
    float* sb2 = (float*)(smx + P_SB2);
    const int tid = threadIdx.x, lane = tid & 31, wid = tid >> 5;
    const int wm = wid & 3, wn = wid >> 2;

    if (tid < 128)      sb1[tid] = b1g[tid];
    else if (tid < 256) sb2[tid - 128] = b2g[tid - 128];
    {
        const uint4* s1 = (const uint4*)((const char*)g_wimg + BW_W1U);
        uint4* d1 = (uint4*)(smx + P_W1);
        for (int i = tid; i < 4224; i += 512) d1[i] = s1[i];
        const uint4* s2 = (const uint4*)((const char*)g_wimg + BW_W2U);
        uint4* d2 = (uint4*)(smx + P_W2H);
        for (int i = tid; i < 4352; i += 512) d2[i] = s2[i];
    }

    for (int tile = blockIdx.x; tile < nTiles; tile += gridDim.x) {
        const int n0 = tile * 128;
        __syncthreads();

        // X chunk0: node_feats hi/lo
        for (int t = tid; t < 128 * 32; t += 512) {
            int row = t >> 5, ch = t & 31;
            int n = n0 + row; if (n >= N) n = N - 1;
            if (ch < 16)
                *(uint4*)(smx + P_XH + row * 272 + ch * 16) = ((const uint4*)(g_nfh + (size_t)n * 128))[ch];
            else
                *(uint4*)(smx + P_XL + row * 272 + (ch - 16) * 16) = ((const uint4*)(g_nfl + (size_t)n * 128))[ch - 16];
        }
        __syncthreads();

        float c[2][4][4];
        #pragma unroll
        for (int i = 0; i < 2; ++i)
            #pragma unroll
            for (int j = 0; j < 4; ++j)
                #pragma unroll
                for (int r = 0; r < 4; ++r) c[i][j][r] = 0.f;
        #pragma unroll
        for (int k = 0; k < 8; ++k)
            gemm_stepA2<272, 528>(c, sb + P_XH, sb + P_XL, sb + P_W1,
                                  k * 32, k * 32, wm, wn, lane);
        __syncthreads();

        // X chunk1: g_agg fp32 -> hi/lo
        for (int t = tid; t < 128 * 16; t += 512) {
            int row = t >> 4, ch = t & 15;
            int n = n0 + row; if (n >= N) n = N - 1;
            const float4* bp = (const float4*)(g_agg + (size_t)n * 128 + ch * 8);
            uint4 hi, lo;
            splitpack8(bp[0], bp[1], hi, lo);
            *(uint4*)(smx + P_XH + row * 272 + ch * 16) = hi;
            *(uint4*)(smx + P_XL + row * 272 + ch * 16) = lo;
        }
        __syncthreads();
        #pragma unroll
        for (int k = 0; k < 8; ++k)
            gemm_stepA2<272, 528>(c, sb + P_XH, sb + P_XL, sb + P_W1,
                                  k * 32, 256 + k * 32, wm, wn, lane);
        __syncthreads();

        // epilogue1: bias+lrelu -> H hi/lo (overlays X region)
        #pragma unroll
        for (int mt = 0; mt < 2; ++mt)
            #pragma unroll
            for (int nt = 0; nt < 4; ++nt) {
                int r0  = wm * 32 + mt * 16 + (lane >> 2);
                int col = wn * 32 + nt * 8 + (lane & 3) * 2;
                float ba = sb1[col], bb = sb1[col + 1];
                float f0 = lrelu(c[mt][nt][0] + ba), f1 = lrelu(c[mt][nt][1] + bb);
                float f2 = lrelu(c[mt][nt][2] + ba), f3 = lrelu(c[mt][nt][3] + bb);
                __half h0 = __float2half_rn(f0), h1 = __float2half_rn(f1);
                __half h2 = __float2half_rn(f2), h3 = __float2half_rn(f3);
                *(uint32_t*)(smx + P_XH + r0 * 272 + col * 2)       = packh2(h0, h1);
                *(uint32_t*)(smx + P_XH + (r0 + 8) * 272 + col * 2) = packh2(h2, h3);
                *(uint32_t*)(smx + P_XL + r0 * 272 + col * 2) =
                    packh2(__float2half_rn(f0 - __half2float(h0)), __float2half_rn(f1 - __half2float(h1)));
                *(uint32_t*)(smx + P_XL + (r0 + 8) * 272 + col * 2) =
                    packh2(__float2half_rn(f2 - __half2float(h2)), __float2half_rn(f3 - __half2float(h3)));
            }
        __syncthreads();

        // GEMM2: K=128, 3-term
        #pragma unroll
        for (int i = 0; i < 2; ++i)
            #pragma unroll
            for (int j = 0; j < 4; ++j)
                #pragma unroll
                for (int r = 0; r < 4; ++r) c[i][j][r] = 0.f;
        #pragma unroll
        for (int k = 0; k < 8; ++k)
            gemm_step3<272, 272>(c, sb + P_XH, sb + P_XL, sb + P_W2H, sb + P_W2L,
                                 k * 32, k * 32, wm, wn, lane);

        // epilogue2: bias + v4 stores
        {
            const int q = lane & 3;
            const int Lb = wn * 32 + q * 8;
            float c0 = sb2[Lb],     c1 = sb2[Lb + 1], c2 = sb2[Lb + 2], c3 = sb2[Lb + 3];
            float c4 = sb2[Lb + 4], c5 = sb2[Lb + 5], c6 = sb2[Lb + 6], c7 = sb2[Lb + 7];
            #pragma unroll
            for (int mt = 0; mt < 2; ++mt) {
                int r = wm * 32 + mt * 16 + (lane >> 2);
                int nA = n0 + r, nB = n0 + r + 8;
                if (nA < N) {
                    float4* p = (float4*)(out + (size_t)nA * 128 + Lb);
                    p[0] = make_float4(c[mt][0][0] + c0, c[mt][0][1] + c1, c[mt][1][0] + c2, c[mt][1][1] + c3);
                    p[1] = make_float4(c[mt][2][0] + c4, c[mt][2][1] + c5, c[mt][3][0] + c6, c[mt][3][1] + c7);
                }
                if (nB < N) {
                    float4* p = (float4*)(out + (size_t)nB * 128 + Lb);
                    p[0] = make_float4(c[mt][0][2] + c0, c[mt][0][3] + c1, c[mt][1][2] + c2, c[mt][1][3] + c3);
                    p[1] = make_float4(c[mt][2][2] + c4, c[mt][2][3] + c5, c[mt][3][2] + c6, c[mt][3][3] + c7);
                }
            }
        }
    }
}

// ---------------------------------------------------------------------------

extern "C" void kernel_launch(void* const* d_in, const int* in_sizes, int n_in,
                              void* d_out, int out_size)
{
    const float* node_feats = (const float*)d_in[0];
    const float* edge_feats = (const float*)d_in[1];
    const float* msg_w1     = (const float*)d_in[2];
    const float* msg_b1     = (const float*)d_in[3];
    const float* msg_w2     = (const float*)d_in[4];
    const float* msg_b2     = (const float*)d_in[5];
    const float* upd_w1     = (const float*)d_in[6];
    const float* upd_b1     = (const float*)d_in[7];
    const float* upd_w2     = (const float*)d_in[8];
    const float* upd_b2     = (const float*)d_in[9];
    const void*  edge_index = d_in[10];

    const int N = in_sizes[0] / 128;   // 50000
    const int E = in_sizes[1] / 64;    // 800000
    const int nTiles  = (E + 127) / 128;
    const int nNTiles = (N + 127) / 128;

    cudaFuncSetAttribute(edge_mma_kernel, cudaFuncAttributeMaxDynamicSharedMemorySize, E_DYN);
    cudaFuncSetAttribute(node_mma_kernel, cudaFuncAttributeMaxDynamicSharedMemorySize, P_DYN);

    prep_kernel<<<1024, 256>>>(node_feats, msg_w1, msg_w2,
                               upd_w1, upd_w2, edge_index, N, E);

    edge_mma_kernel<<<148, 512, E_DYN>>>(edge_feats, msg_b1, msg_b2, E, nTiles);

    node_mma_kernel<<<148, 512, P_DYN>>>(upd_b1, upd_b2, (float*)d_out, N, nNTiles);
}